// round 2
// baseline (speedup 1.0000x reference)
#include <cuda_runtime.h>
#include <math_constants.h>

#define Ssz   50
#define Hsz   256
#define NPT   3200
#define TILE  16
#define EROWS 32

typedef unsigned long long u64;
union F2 { u64 u; float2 f; };

__device__ __forceinline__ u64 fma2(u64 a, u64 b, u64 c){
    u64 d; asm("fma.rn.f32x2 %0, %1, %2, %3;" : "=l"(d) : "l"(a), "l"(b), "l"(c));
    return d;
}
__device__ __forceinline__ u64 dup2(float x){
    F2 t; t.f.x = x; t.f.y = x; return t.u;
}

// ---------------- scratch (static device globals; no allocation) ----------------
static __device__ float  g_enc_t[(size_t)9600 * Ssz * Hsz];   // 491.5 MB
static __device__ float4 g_wpack[512 * 256];                  // gate-interleaved [kk][k] -> (i,f,g,o)
static __device__ float4 g_bias4[256];                        // combined bias per k, 4 gates
static __device__ float4 g_w2pack[64 * 256];                  // W2T packed over h in float4
static __device__ float4 g_w1pack[64 * 256];                  // W1T packed over h in float4

// ---------------- fast activations ----------------
__device__ __forceinline__ float fsig(float x){
    return __fdividef(1.f, 1.f + __expf(-x));
}
__device__ __forceinline__ float ftanh(float x){
    return 1.f - __fdividef(2.f, 1.f + __expf(2.f * x));
}

// ---------------- weight packing ----------------
__global__ void pack_gates_kernel(const float* __restrict__ Wih, const float* __restrict__ Whh,
                                  const float* __restrict__ bih, const float* __restrict__ bhh){
    int kk = blockIdx.x, k = threadIdx.x;          // kk in [0,512): 0..255 -> x path, 256..511 -> h path
    const float* src = (kk < 256) ? Wih : Whh;
    int col = kk & 255;
    float4 v;
    v.x = src[(size_t)(k      ) * 256 + col];
    v.y = src[(size_t)(k + 256) * 256 + col];
    v.z = src[(size_t)(k + 512) * 256 + col];
    v.w = src[(size_t)(k + 768) * 256 + col];
    g_wpack[kk * 256 + k] = v;
    if (kk == 0){
        float4 b;
        b.x = bih[k]       + bhh[k];
        b.y = bih[k + 256] + bhh[k + 256];
        b.z = bih[k + 512] + bhh[k + 512];
        b.w = bih[k + 768] + bhh[k + 768];
        g_bias4[k] = b;
    }
}

__global__ void pack_w_kernel(const float* __restrict__ W2, const float* __restrict__ W1){
    int h4 = blockIdx.x, k = threadIdx.x;
    g_w2pack[h4 * 256 + k] = ((const float4*)(W2 + (size_t)k * 256))[h4];  // W2T[h..h+3][k]
    g_w1pack[h4 * 256 + k] = ((const float4*)(W1 + (size_t)k * 256))[h4];  // W1T[h..h+3][k]
}

// ---------------- enc_t = enc @ W1^T (fma2, pair over h, zero movs) ----------------
__global__ __launch_bounds__(256, 2) void enc_t_kernel(const float* __restrict__ e0,
                                                       const float* __restrict__ e1,
                                                       const float* __restrict__ e2){
    __shared__ float in_s[EROWS * 256];            // 32 rows x 256 floats = 32 KB
    int b  = blockIdx.x;                           // 0..14999
    int t  = b / 5000;
    int rb = (b % 5000) * EROWS;
    const float* enc = (t == 0) ? e0 : ((t == 1) ? e1 : e2);
    const float4* src = (const float4*)(enc + (size_t)rb * Hsz);
    int k = threadIdx.x;
    for (int i = k; i < EROWS * 64; i += 256) ((float4*)in_s)[i] = src[i];
    __syncthreads();

    u64 acc[EROWS];
    {
        F2 z; z.f.x = 0.f; z.f.y = 0.f;
#pragma unroll
        for (int r = 0; r < EROWS; r++) acc[r] = z.u;
    }

#pragma unroll 1
    for (int h4 = 0; h4 < 64; h4++){
        ulonglong2 w = *(const ulonglong2*)(&g_w1pack[h4 * 256 + k]);
#pragma unroll
        for (int r = 0; r < EROWS; r++){
            ulonglong2 v = *(const ulonglong2*)(&in_s[r * 256 + h4 * 4]);
            acc[r] = fma2(v.x, w.x, acc[r]);
            acc[r] = fma2(v.y, w.y, acc[r]);
        }
    }
    float* dst = g_enc_t + ((size_t)t * 160000 + rb) * Hsz;
#pragma unroll
    for (int r = 0; r < EROWS; r++){
        F2 a; a.u = acc[r];
        dst[(size_t)r * Hsz + k] = a.f.x + a.f.y;
    }
}

// ---------------- recurrence: TILE rows per CTA, all 50 steps ----------------
#define T_STRIDE 18                                 // in_catT row stride (floats): even -> 8B aligned pairs
#define R_STRIDE 260                                // h_row/dec_s row stride (floats): mult of 4 -> 16B aligned

__global__ __launch_bounds__(256, 2) void recur_kernel(const float* __restrict__ e0,
                                                       const float* __restrict__ e1,
                                                       const float* __restrict__ e2,
                                                       const float* __restrict__ vt,
                                                       float* __restrict__ out){
    extern __shared__ float smem[];
    float* in_catT = smem;                               // [512][18]  (k-major: [k][r])
    float* h_row   = smem + 512 * T_STRIDE;              // [16][260]  row-major h
    float* dec_s   = h_row + TILE * R_STRIDE;            // [16][260]  row-major dec
    float* u_s     = dec_s + TILE * R_STRIDE;            // [16][52]
    float* vt_s    = u_s + TILE * 52;                    // [256]
    int*   idx_s   = (int*)(vt_s + 256);                 // [16]

    const int tid  = threadIdx.x;                  // = output index k in [0,256)
    const int bid  = blockIdx.x;                   // 0..599
    const int t    = bid / 200;
    const int n0   = (bid % 200) * TILE;
    const int wid  = tid >> 5, lane = tid & 31;

    const float* enc  = (t == 0) ? e0 : ((t == 1) ? e1 : e2);
    const float* encb = enc + (size_t)n0 * (Ssz * Hsz);
    const float* etb  = g_enc_t + (size_t)bid * TILE * Ssz * Hsz;
    float* score_out  = out + (size_t)t * 8160000 + (size_t)n0 * 2500;
    float* idx_out    = out + (size_t)t * 8160000 + 8000000 + (size_t)n0 * 50;

    vt_s[tid] = vt[tid];

    // init: c = h0 = sum_s enc[row,s,:], x = 0
    float c[TILE];
#pragma unroll
    for (int r = 0; r < TILE; r++){
        float s = 0.f;
        const float* p = encb + (size_t)r * Ssz * Hsz + tid;
#pragma unroll 1
        for (int ss = 0; ss < Ssz; ss++) s += p[ss * Hsz];
        c[r] = s;
        in_catT[(256 + tid) * T_STRIDE + r] = s;   // h transposed
        in_catT[tid * T_STRIDE + r] = 0.f;         // x transposed = 0
    }
    __syncthreads();

#pragma unroll 1
    for (int step = 0; step < Ssz; step++){
        // ---- Phase A: gates = [x|h] @ Wcat^T  (fma2, row-pairs) ----
        u64 accp[8][4];
        {
            F2 z; z.f.x = 0.f; z.f.y = 0.f;
#pragma unroll
            for (int rp = 0; rp < 8; rp++)
#pragma unroll
                for (int g = 0; g < 4; g++) accp[rp][g] = z.u;
        }

#pragma unroll 1
        for (int kk4 = 0; kk4 < 128; kk4++){
            const float4* wp = g_wpack + (kk4 * 4) * 256 + tid;
            float4 w0 = wp[0];
            float4 w1 = wp[256];
            float4 w2 = wp[512];
            float4 w3 = wp[768];
#pragma unroll
            for (int k = 0; k < 4; k++){
                float4 wk = (k == 0) ? w0 : ((k == 1) ? w1 : ((k == 2) ? w2 : w3));
                u64 wi = dup2(wk.x), wf = dup2(wk.y), wg = dup2(wk.z), wo = dup2(wk.w);
                const float* base = in_catT + (kk4 * 4 + k) * T_STRIDE;
#pragma unroll
                for (int rp = 0; rp < 8; rp++){
                    u64 a = *(const u64*)(base + 2 * rp);   // (v[2rp], v[2rp+1]), broadcast
                    accp[rp][0] = fma2(a, wi, accp[rp][0]);
                    accp[rp][1] = fma2(a, wf, accp[rp][1]);
                    accp[rp][2] = fma2(a, wg, accp[rp][2]);
                    accp[rp][3] = fma2(a, wo, accp[rp][3]);
                }
            }
        }
        __syncthreads();   // all reads of in_catT done before h is overwritten

        // ---- Phase B: LSTM cell, update c, write h (transposed + row-major) ----
        {
            float4 bias = g_bias4[tid];
#pragma unroll
            for (int rp = 0; rp < 8; rp++){
                F2 ai, af, ag, ao;
                ai.u = accp[rp][0]; af.u = accp[rp][1];
                ag.u = accp[rp][2]; ao.u = accp[rp][3];
#pragma unroll
                for (int hh = 0; hh < 2; hh++){
                    int r = 2 * rp + hh;
                    float xi = hh ? ai.f.y : ai.f.x;
                    float xf = hh ? af.f.y : af.f.x;
                    float xg = hh ? ag.f.y : ag.f.x;
                    float xo = hh ? ao.f.y : ao.f.x;
                    float gi = fsig (xi + bias.x);
                    float gf = fsig (xf + bias.y);
                    float gg = ftanh(xg + bias.z);
                    float go = fsig (xo + bias.w);
                    float cn = fmaf(gf, c[r], gi * gg);
                    c[r] = cn;
                    float h = go * ftanh(cn);
                    in_catT[(256 + tid) * T_STRIDE + r] = h;
                    h_row[r * R_STRIDE + tid] = h;
                }
            }
        }
        __syncthreads();   // h visible

        // ---- Phase C: dec = h @ W2^T  (fma2, pair over h, zero movs) ----
        {
            u64 dacc[TILE];
            {
                F2 z; z.f.x = 0.f; z.f.y = 0.f;
#pragma unroll
                for (int r = 0; r < TILE; r++) dacc[r] = z.u;
            }
#pragma unroll 1
            for (int h4 = 0; h4 < 64; h4++){
                ulonglong2 w = *(const ulonglong2*)(&g_w2pack[h4 * 256 + tid]);
#pragma unroll
                for (int r = 0; r < TILE; r++){
                    ulonglong2 v = *(const ulonglong2*)(&h_row[r * R_STRIDE + h4 * 4]);
                    dacc[r] = fma2(v.x, w.x, dacc[r]);
                    dacc[r] = fma2(v.y, w.y, dacc[r]);
                }
            }
#pragma unroll
            for (int r = 0; r < TILE; r++){
                F2 a; a.u = dacc[r];
                dec_s[r * R_STRIDE + tid] = a.f.x + a.f.y;
            }
        }
        __syncthreads();   // dec visible

        // ---- Phase D: u[r][s] = sum_k tanh(enc_t + dec) * vt ----
#pragma unroll 1
        for (int task = wid; task < TILE * Ssz; task += 8){
            int r  = task / Ssz;
            int ss = task - r * Ssz;
            const float4* ep = (const float4*)(etb + ((size_t)r * Ssz + ss) * Hsz);
            float4 elo = ep[lane];
            float4 ehi = ep[32 + lane];
            float4 dlo = *(const float4*)(&dec_s[r * R_STRIDE + 4 * lane]);
            float4 dhi = *(const float4*)(&dec_s[r * R_STRIDE + 128 + 4 * lane]);
            float4 v0  = *(const float4*)(&vt_s[4 * lane]);
            float4 v1  = *(const float4*)(&vt_s[128 + 4 * lane]);
            float p0, p1;
            p0 = ftanh(elo.x + dlo.x) * v0.x;
            p1 = ftanh(elo.y + dlo.y) * v0.y;
            p0 = fmaf(ftanh(elo.z + dlo.z), v0.z, p0);
            p1 = fmaf(ftanh(elo.w + dlo.w), v0.w, p1);
            p0 = fmaf(ftanh(ehi.x + dhi.x), v1.x, p0);
            p1 = fmaf(ftanh(ehi.y + dhi.y), v1.y, p1);
            p0 = fmaf(ftanh(ehi.z + dhi.z), v1.z, p0);
            p1 = fmaf(ftanh(ehi.w + dhi.w), v1.w, p1);
            float p = p0 + p1;
#pragma unroll
            for (int off = 16; off; off >>= 1)
                p += __shfl_xor_sync(0xffffffffu, p, off);
            if (lane == 0) u_s[r * 52 + ss] = p;
        }
        __syncthreads();

        // ---- Phase E: softmax + argmax (first-max tiebreak), write outputs ----
#pragma unroll 1
        for (int rr = 0; rr < 2; rr++){
            int r = wid + rr * 8;
            float ua = u_s[r * 52 + lane];
            float ub = (lane + 32 < Ssz) ? u_s[r * 52 + lane + 32] : -CUDART_INF_F;
            float bm = ua; int bi = lane;
            if (ub > bm){ bm = ub; bi = lane + 32; }
#pragma unroll
            for (int off = 16; off; off >>= 1){
                float vm = __shfl_xor_sync(0xffffffffu, bm, off);
                int   vi = __shfl_xor_sync(0xffffffffu, bi, off);
                if (vm > bm || (vm == bm && vi < bi)){ bm = vm; bi = vi; }
            }
            float ea = __expf(ua - bm);
            float eb = (lane + 32 < Ssz) ? __expf(ub - bm) : 0.f;
            float sm = ea + eb;
#pragma unroll
            for (int off = 16; off; off >>= 1)
                sm += __shfl_xor_sync(0xffffffffu, sm, off);
            float inv = 1.0f / sm;
            float* so = score_out + (size_t)r * 2500 + step * 50;
            so[lane] = ea * inv;
            if (lane + 32 < Ssz) so[lane + 32] = eb * inv;
            if (lane == 0){
                idx_s[r] = bi;
                idx_out[(size_t)r * 50 + step] = (float)bi;
            }
        }
        __syncthreads();

        // ---- Phase F: gather x_next = enc[row, idx, :] -> transposed x ----
#pragma unroll
        for (int r = 0; r < TILE; r++){
            int ii = idx_s[r];
            in_catT[tid * T_STRIDE + r] = encb[(size_t)r * Ssz * Hsz + (size_t)ii * Hsz + tid];
        }
        __syncthreads();
    }
}

// ---------------- launch ----------------
#define RECUR_SMEM ((512 * T_STRIDE + 2 * TILE * R_STRIDE + TILE * 52 + 256 + 16) * 4)

extern "C" void kernel_launch(void* const* d_in, const int* in_sizes, int n_in,
                              void* d_out, int out_size){
    const float* home = (const float*)d_in[0];
    const float* vis  = (const float*)d_in[1];
    const float* team = (const float*)d_in[2];
    const float* Wih  = (const float*)d_in[3];
    const float* Whh  = (const float*)d_in[4];
    const float* bih  = (const float*)d_in[5];
    const float* bhh  = (const float*)d_in[6];
    const float* W1   = (const float*)d_in[7];
    const float* W2   = (const float*)d_in[8];
    const float* vt   = (const float*)d_in[9];
    float* out = (float*)d_out;

    cudaFuncSetAttribute(recur_kernel, cudaFuncAttributeMaxDynamicSharedMemorySize, RECUR_SMEM);

    pack_gates_kernel<<<512, 256>>>(Wih, Whh, bih, bhh);
    pack_w_kernel<<<64, 256>>>(W2, W1);
    enc_t_kernel<<<15000, 256>>>(home, vis, team);
    recur_kernel<<<600, 256, RECUR_SMEM>>>(home, vis, team, vt, out);
}

// round 3
// speedup vs baseline: 1.0033x; 1.0033x over previous
#include <cuda_runtime.h>
#include <math_constants.h>

#define Ssz   50
#define Hsz   256
#define NPT   3200
#define TILE  16
#define EROWS 32

typedef unsigned long long u64;
union F2 { u64 u; float2 f; };

__device__ __forceinline__ u64 fma2(u64 a, u64 b, u64 c){
    u64 d; asm("fma.rn.f32x2 %0, %1, %2, %3;" : "=l"(d) : "l"(a), "l"(b), "l"(c));
    return d;
}
__device__ __forceinline__ u64 dup2(float x){
    F2 t; t.f.x = x; t.f.y = x; return t.u;
}

// ---------------- scratch (static device globals; no allocation) ----------------
static __device__ float  g_enc_t[(size_t)9600 * Ssz * Hsz];   // 491.5 MB
static __device__ float4 g_wpack[512 * 256];                  // gate-interleaved [kk][k] -> (i,f,g,o)
static __device__ float4 g_bias4[256];                        // combined bias per k, 4 gates
static __device__ float4 g_w2pack[64 * 256];                  // W2T packed over h in float4
static __device__ float4 g_w1pack[64 * 256];                  // W1T packed over h in float4

// ---------------- fast activations ----------------
__device__ __forceinline__ float fsig(float x){
    return __fdividef(1.f, 1.f + __expf(-x));
}
__device__ __forceinline__ float ftanh(float x){
    return 1.f - __fdividef(2.f, 1.f + __expf(2.f * x));
}

// ---------------- weight packing ----------------
__global__ void pack_gates_kernel(const float* __restrict__ Wih, const float* __restrict__ Whh,
                                  const float* __restrict__ bih, const float* __restrict__ bhh){
    int kk = blockIdx.x, k = threadIdx.x;          // kk in [0,512): 0..255 -> x path, 256..511 -> h path
    const float* src = (kk < 256) ? Wih : Whh;
    int col = kk & 255;
    float4 v;
    v.x = src[(size_t)(k      ) * 256 + col];
    v.y = src[(size_t)(k + 256) * 256 + col];
    v.z = src[(size_t)(k + 512) * 256 + col];
    v.w = src[(size_t)(k + 768) * 256 + col];
    g_wpack[kk * 256 + k] = v;
    if (kk == 0){
        float4 b;
        b.x = bih[k]       + bhh[k];
        b.y = bih[k + 256] + bhh[k + 256];
        b.z = bih[k + 512] + bhh[k + 512];
        b.w = bih[k + 768] + bhh[k + 768];
        g_bias4[k] = b;
    }
}

__global__ void pack_w_kernel(const float* __restrict__ W2, const float* __restrict__ W1){
    int h4 = blockIdx.x, k = threadIdx.x;
    g_w2pack[h4 * 256 + k] = ((const float4*)(W2 + (size_t)k * 256))[h4];  // W2T[h..h+3][k]
    g_w1pack[h4 * 256 + k] = ((const float4*)(W1 + (size_t)k * 256))[h4];  // W1T[h..h+3][k]
}

// ---------------- enc_t = enc @ W1^T (fma2, pair over h, zero movs) ----------------
__global__ __launch_bounds__(256, 2) void enc_t_kernel(const float* __restrict__ e0,
                                                       const float* __restrict__ e1,
                                                       const float* __restrict__ e2){
    __shared__ float in_s[EROWS * 256];            // 32 rows x 256 floats = 32 KB
    int b  = blockIdx.x;                           // 0..14999
    int t  = b / 5000;
    int rb = (b % 5000) * EROWS;
    const float* enc = (t == 0) ? e0 : ((t == 1) ? e1 : e2);
    const float4* src = (const float4*)(enc + (size_t)rb * Hsz);
    int k = threadIdx.x;
    for (int i = k; i < EROWS * 64; i += 256) ((float4*)in_s)[i] = src[i];
    __syncthreads();

    u64 acc[EROWS];
    {
        F2 z; z.f.x = 0.f; z.f.y = 0.f;
#pragma unroll
        for (int r = 0; r < EROWS; r++) acc[r] = z.u;
    }

#pragma unroll 1
    for (int h4 = 0; h4 < 64; h4++){
        ulonglong2 w = *(const ulonglong2*)(&g_w1pack[h4 * 256 + k]);
#pragma unroll
        for (int r = 0; r < EROWS; r++){
            ulonglong2 v = *(const ulonglong2*)(&in_s[r * 256 + h4 * 4]);
            acc[r] = fma2(v.x, w.x, acc[r]);
            acc[r] = fma2(v.y, w.y, acc[r]);
        }
    }
    float* dst = g_enc_t + ((size_t)t * 160000 + rb) * Hsz;
#pragma unroll
    for (int r = 0; r < EROWS; r++){
        F2 a; a.u = acc[r];
        dst[(size_t)r * Hsz + k] = a.f.x + a.f.y;
    }
}

// ---------------- recurrence: TILE rows per CTA, all 50 steps ----------------
#define T_STRIDE 18                                 // in_catT row stride (floats): even -> 8B aligned pairs
#define R_STRIDE 260                                // h_row/dec_s row stride (floats): mult of 4 -> 16B aligned

__global__ __launch_bounds__(256, 2) void recur_kernel(const float* __restrict__ e0,
                                                       const float* __restrict__ e1,
                                                       const float* __restrict__ e2,
                                                       const float* __restrict__ vt,
                                                       float* __restrict__ out){
    extern __shared__ float smem[];
    float* in_catT = smem;                               // [512][18]  (k-major: [k][r])
    float* h_row   = smem + 512 * T_STRIDE;              // [16][260]  row-major h
    float* dec_s   = h_row + TILE * R_STRIDE;            // [16][260]  row-major dec
    float* u_s     = dec_s + TILE * R_STRIDE;            // [16][52]
    float* vt_s    = u_s + TILE * 52;                    // [256]
    int*   idx_s   = (int*)(vt_s + 256);                 // [16]

    const int tid  = threadIdx.x;                  // = output index k in [0,256)
    const int bid  = blockIdx.x;                   // 0..599
    const int t    = bid / 200;
    const int n0   = (bid % 200) * TILE;
    const int wid  = tid >> 5, lane = tid & 31;

    const float* enc  = (t == 0) ? e0 : ((t == 1) ? e1 : e2);
    const float* encb = enc + (size_t)n0 * (Ssz * Hsz);
    const float* etb  = g_enc_t + (size_t)bid * TILE * Ssz * Hsz;
    float* score_out  = out + (size_t)t * 8160000 + (size_t)n0 * 2500;
    float* idx_out    = out + (size_t)t * 8160000 + 8000000 + (size_t)n0 * 50;

    vt_s[tid] = vt[tid];

    // init: c = h0 = sum_s enc[row,s,:], x = 0
    float c[TILE];
#pragma unroll
    for (int r = 0; r < TILE; r++){
        float s = 0.f;
        const float* p = encb + (size_t)r * Ssz * Hsz + tid;
#pragma unroll 1
        for (int ss = 0; ss < Ssz; ss++) s += p[ss * Hsz];
        c[r] = s;
        in_catT[(256 + tid) * T_STRIDE + r] = s;   // h transposed
        in_catT[tid * T_STRIDE + r] = 0.f;         // x transposed = 0
    }
    __syncthreads();

#pragma unroll 1
    for (int step = 0; step < Ssz; step++){
        // ---- Phase A: gates = [x|h] @ Wcat^T  (fma2, row-pairs) ----
        u64 accp[8][4];
        {
            F2 z; z.f.x = 0.f; z.f.y = 0.f;
#pragma unroll
            for (int rp = 0; rp < 8; rp++)
#pragma unroll
                for (int g = 0; g < 4; g++) accp[rp][g] = z.u;
        }

#pragma unroll 1
        for (int kk4 = 0; kk4 < 128; kk4++){
            const float4* wp = g_wpack + (kk4 * 4) * 256 + tid;
            float4 w0 = wp[0];
            float4 w1 = wp[256];
            float4 w2 = wp[512];
            float4 w3 = wp[768];
#pragma unroll
            for (int k = 0; k < 4; k++){
                float4 wk = (k == 0) ? w0 : ((k == 1) ? w1 : ((k == 2) ? w2 : w3));
                u64 wi = dup2(wk.x), wf = dup2(wk.y), wg = dup2(wk.z), wo = dup2(wk.w);
                const float* base = in_catT + (kk4 * 4 + k) * T_STRIDE;
#pragma unroll
                for (int rp = 0; rp < 8; rp++){
                    u64 a = *(const u64*)(base + 2 * rp);   // (v[2rp], v[2rp+1]), broadcast
                    accp[rp][0] = fma2(a, wi, accp[rp][0]);
                    accp[rp][1] = fma2(a, wf, accp[rp][1]);
                    accp[rp][2] = fma2(a, wg, accp[rp][2]);
                    accp[rp][3] = fma2(a, wo, accp[rp][3]);
                }
            }
        }
        __syncthreads();   // all reads of in_catT done before h is overwritten

        // ---- Phase B: LSTM cell, update c, write h (transposed + row-major) ----
        {
            float4 bias = g_bias4[tid];
#pragma unroll
            for (int rp = 0; rp < 8; rp++){
                F2 ai, af, ag, ao;
                ai.u = accp[rp][0]; af.u = accp[rp][1];
                ag.u = accp[rp][2]; ao.u = accp[rp][3];
#pragma unroll
                for (int hh = 0; hh < 2; hh++){
                    int r = 2 * rp + hh;
                    float xi = hh ? ai.f.y : ai.f.x;
                    float xf = hh ? af.f.y : af.f.x;
                    float xg = hh ? ag.f.y : ag.f.x;
                    float xo = hh ? ao.f.y : ao.f.x;
                    float gi = fsig (xi + bias.x);
                    float gf = fsig (xf + bias.y);
                    float gg = ftanh(xg + bias.z);
                    float go = fsig (xo + bias.w);
                    float cn = fmaf(gf, c[r], gi * gg);
                    c[r] = cn;
                    float h = go * ftanh(cn);
                    in_catT[(256 + tid) * T_STRIDE + r] = h;
                    h_row[r * R_STRIDE + tid] = h;
                }
            }
        }
        __syncthreads();   // h visible

        // ---- Phase C: dec = h @ W2^T  (fma2, pair over h, zero movs) ----
        {
            u64 dacc[TILE];
            {
                F2 z; z.f.x = 0.f; z.f.y = 0.f;
#pragma unroll
                for (int r = 0; r < TILE; r++) dacc[r] = z.u;
            }
#pragma unroll 1
            for (int h4 = 0; h4 < 64; h4++){
                ulonglong2 w = *(const ulonglong2*)(&g_w2pack[h4 * 256 + tid]);
#pragma unroll
                for (int r = 0; r < TILE; r++){
                    ulonglong2 v = *(const ulonglong2*)(&h_row[r * R_STRIDE + h4 * 4]);
                    dacc[r] = fma2(v.x, w.x, dacc[r]);
                    dacc[r] = fma2(v.y, w.y, dacc[r]);
                }
            }
#pragma unroll
            for (int r = 0; r < TILE; r++){
                F2 a; a.u = dacc[r];
                dec_s[r * R_STRIDE + tid] = a.f.x + a.f.y;
            }
        }
        __syncthreads();   // dec visible

        // ---- Phase D: u[r][s] = sum_k tanh(enc_t + dec) * vt ----
#pragma unroll 1
        for (int task = wid; task < TILE * Ssz; task += 8){
            int r  = task / Ssz;
            int ss = task - r * Ssz;
            const float4* ep = (const float4*)(etb + ((size_t)r * Ssz + ss) * Hsz);
            float4 elo = ep[lane];
            float4 ehi = ep[32 + lane];
            float4 dlo = *(const float4*)(&dec_s[r * R_STRIDE + 4 * lane]);
            float4 dhi = *(const float4*)(&dec_s[r * R_STRIDE + 128 + 4 * lane]);
            float4 v0  = *(const float4*)(&vt_s[4 * lane]);
            float4 v1  = *(const float4*)(&vt_s[128 + 4 * lane]);
            float p0, p1;
            p0 = ftanh(elo.x + dlo.x) * v0.x;
            p1 = ftanh(elo.y + dlo.y) * v0.y;
            p0 = fmaf(ftanh(elo.z + dlo.z), v0.z, p0);
            p1 = fmaf(ftanh(elo.w + dlo.w), v0.w, p1);
            p0 = fmaf(ftanh(ehi.x + dhi.x), v1.x, p0);
            p1 = fmaf(ftanh(ehi.y + dhi.y), v1.y, p1);
            p0 = fmaf(ftanh(ehi.z + dhi.z), v1.z, p0);
            p1 = fmaf(ftanh(ehi.w + dhi.w), v1.w, p1);
            float p = p0 + p1;
#pragma unroll
            for (int off = 16; off; off >>= 1)
                p += __shfl_xor_sync(0xffffffffu, p, off);
            if (lane == 0) u_s[r * 52 + ss] = p;
        }
        __syncthreads();

        // ---- Phase E: softmax + argmax (first-max tiebreak), write outputs ----
#pragma unroll 1
        for (int rr = 0; rr < 2; rr++){
            int r = wid + rr * 8;
            float ua = u_s[r * 52 + lane];
            float ub = (lane + 32 < Ssz) ? u_s[r * 52 + lane + 32] : -CUDART_INF_F;
            float bm = ua; int bi = lane;
            if (ub > bm){ bm = ub; bi = lane + 32; }
#pragma unroll
            for (int off = 16; off; off >>= 1){
                float vm = __shfl_xor_sync(0xffffffffu, bm, off);
                int   vi = __shfl_xor_sync(0xffffffffu, bi, off);
                if (vm > bm || (vm == bm && vi < bi)){ bm = vm; bi = vi; }
            }
            float ea = __expf(ua - bm);
            float eb = (lane + 32 < Ssz) ? __expf(ub - bm) : 0.f;
            float sm = ea + eb;
#pragma unroll
            for (int off = 16; off; off >>= 1)
                sm += __shfl_xor_sync(0xffffffffu, sm, off);
            float inv = 1.0f / sm;
            float* so = score_out + (size_t)r * 2500 + step * 50;
            so[lane] = ea * inv;
            if (lane + 32 < Ssz) so[lane + 32] = eb * inv;
            if (lane == 0){
                idx_s[r] = bi;
                idx_out[(size_t)r * 50 + step] = (float)bi;
            }
        }
        __syncthreads();

        // ---- Phase F: gather x_next = enc[row, idx, :] -> transposed x ----
#pragma unroll
        for (int r = 0; r < TILE; r++){
            int ii = idx_s[r];
            in_catT[tid * T_STRIDE + r] = encb[(size_t)r * Ssz * Hsz + (size_t)ii * Hsz + tid];
        }
        __syncthreads();
    }
}

// ---------------- launch ----------------
#define RECUR_SMEM ((512 * T_STRIDE + 2 * TILE * R_STRIDE + TILE * 52 + 256 + 16) * 4)

extern "C" void kernel_launch(void* const* d_in, const int* in_sizes, int n_in,
                              void* d_out, int out_size){
    const float* home = (const float*)d_in[0];
    const float* vis  = (const float*)d_in[1];
    const float* team = (const float*)d_in[2];
    const float* Wih  = (const float*)d_in[3];
    const float* Whh  = (const float*)d_in[4];
    const float* bih  = (const float*)d_in[5];
    const float* bhh  = (const float*)d_in[6];
    const float* W1   = (const float*)d_in[7];
    const float* W2   = (const float*)d_in[8];
    const float* vt   = (const float*)d_in[9];
    float* out = (float*)d_out;

    cudaFuncSetAttribute(recur_kernel, cudaFuncAttributeMaxDynamicSharedMemorySize, RECUR_SMEM);

    pack_gates_kernel<<<512, 256>>>(Wih, Whh, bih, bhh);
    pack_w_kernel<<<64, 256>>>(W2, W1);
    enc_t_kernel<<<15000, 256>>>(home, vis, team);
    recur_kernel<<<600, 256, RECUR_SMEM>>>(home, vis, team, vt, out);
}

// round 5
// speedup vs baseline: 1.3911x; 1.3865x over previous
#include <cuda_runtime.h>
#include <cuda_bf16.h>
#include <math_constants.h>
#include <cstdint>

#define Ssz  50
#define NPT  3200
#define NROW 9600
#define ERT  160000
#define NB   1280

// ================= static device scratch (no allocation) =================
static __device__ __nv_bfloat16 g_es0[(size_t)480000*256], g_es1[(size_t)480000*256], g_es2[(size_t)480000*256];
static __device__ float g_eih0[(size_t)ERT*NB], g_eih1[(size_t)ERT*NB], g_eih2[(size_t)ERT*NB];
static __device__ __nv_bfloat16 g_h0s[NROW*256], g_h1s[NROW*256], g_h2s[NROW*256];
static __device__ float g_c[NROW*256];
static __device__ float g_graw[(size_t)NROW*NB];
static __device__ __nv_bfloat16 g_bs0[NB*256], g_bs1[NB*256], g_bs2[NB*256];   // [Whh;W2] splits
static __device__ __nv_bfloat16 g_bp0[NB*256], g_bp1[NB*256], g_bp2[NB*256];   // [Wih;W1] splits
static __device__ float g_bias[1024];
static __device__ int   g_idx[NROW];

__device__ __forceinline__ float* eih_ptr(int t){ return (t==0)?g_eih0:((t==1)?g_eih1:g_eih2); }
__device__ __forceinline__ void split3(float v, __nv_bfloat16& a, __nv_bfloat16& b, __nv_bfloat16& c){
    a = __float2bfloat16(v);  float r  = v - __bfloat162float(a);
    b = __float2bfloat16(r);  float r2 = r - __bfloat162float(b);
    c = __float2bfloat16(r2);
}
__device__ __forceinline__ float fsig(float x){ return __fdividef(1.f, 1.f + __expf(-x)); }
__device__ __forceinline__ float ftanh(float x){ return 1.f - __fdividef(2.f, 1.f + __expf(2.f*x)); }

// ================= baseline-PTX tensor helpers (sm_80-class, valid on sm_103) =================
__device__ __forceinline__ uint32_t smem_u32(const void* p){
    uint32_t a;
    asm("{ .reg .u64 t; cvta.to.shared.u64 t, %1; cvt.u32.u64 %0, t; }" : "=r"(a) : "l"(p));
    return a;
}
__device__ __forceinline__ void ldsm4(uint32_t* r, uint32_t addr){
    asm volatile("ldmatrix.sync.aligned.m8n8.x4.shared.b16 {%0,%1,%2,%3}, [%4];"
        : "=r"(r[0]), "=r"(r[1]), "=r"(r[2]), "=r"(r[3]) : "r"(addr));
}
__device__ __forceinline__ void mma16816(float* c, const uint32_t* a, const uint32_t* b){
    asm volatile("mma.sync.aligned.m16n8k16.row.col.f32.bf16.bf16.f32 "
        "{%0,%1,%2,%3}, {%4,%5,%6,%7}, {%8,%9}, {%0,%1,%2,%3};"
        : "+f"(c[0]), "+f"(c[1]), "+f"(c[2]), "+f"(c[3])
        : "r"(a[0]), "r"(a[1]), "r"(a[2]), "r"(a[3]), "r"(b[0]), "r"(b[1]));
}
__device__ __forceinline__ void cpa16(uint32_t d, const void* s){
    asm volatile("cp.async.cg.shared.global [%0], [%1], 16;" :: "r"(d), "l"(s));
}
#define CP_COMMIT() asm volatile("cp.async.commit_group;" ::: "memory")
#define CP_WAIT0()  asm volatile("cp.async.wait_group 0;" ::: "memory")
#define CP_WAIT1()  asm volatile("cp.async.wait_group 1;" ::: "memory")

// ================= prep kernels =================
__global__ void pack_b_kernel(const float* __restrict__ Whh, const float* __restrict__ W2,
                              const float* __restrict__ Wih, const float* __restrict__ W1,
                              const float* __restrict__ bih, const float* __restrict__ bhh){
    int row = blockIdx.x, k = threadIdx.x, j = row*256 + k;
    float ws = (row < 1024) ? Whh[j] : W2[(size_t)(row-1024)*256 + k];
    float wp = (row < 1024) ? Wih[j] : W1[(size_t)(row-1024)*256 + k];
    split3(ws, g_bs0[j], g_bs1[j], g_bs2[j]);
    split3(wp, g_bp0[j], g_bp1[j], g_bp2[j]);
    if (row < 4) g_bias[j] = bih[j] + bhh[j];
}

__global__ void split_enc_kernel(const float* __restrict__ e0, const float* __restrict__ e1,
                                 const float* __restrict__ e2){
    int k = threadIdx.x;
#pragma unroll
    for (int rr = 0; rr < 8; rr++){
        size_t R = (size_t)blockIdx.x*8 + rr;          // 0..479999
        int t = (int)(R / ERT);
        const float* e = (t==0)?e0:((t==1)?e1:e2);
        float v = e[(R - (size_t)t*ERT)*256 + k];
        split3(v, g_es0[R*256+k], g_es1[R*256+k], g_es2[R*256+k]);
    }
}

__global__ void h0_kernel(const float* __restrict__ e0, const float* __restrict__ e1,
                          const float* __restrict__ e2){
    int r = blockIdx.x, k = threadIdx.x;
    int t = r / NPT, n = r % NPT;
    const float* e = ((t==0)?e0:((t==1)?e1:e2)) + (size_t)n*(Ssz*256) + k;
    float s = 0.f;
#pragma unroll 1
    for (int ss = 0; ss < Ssz; ss++) s += e[ss*256];
    g_c[r*256+k] = s;
    split3(s, g_h0s[r*256+k], g_h1s[r*256+k], g_h2s[r*256+k]);
}

// ================= emulated-fp32 GEMM via mma.sync bf16 =================
// C[M,1280] = A[M,256] @ B[1280,256]^T ; A,B given as 3-way bf16 splits;
// 6 products (00,01,10,11,02,20), fp32 accumulate -> ~fp32 accuracy.
// CTA tile 128x128, 8 warps of 64x32, K staged in 24 chunks of 64 (6 products x 4).
#define ASTR   72                    // smem row stride in bf16 (144B: conflict-free ldmatrix)
#define STAGEB (128*ASTR*2)          // 18432 bytes per tile stage
#define GSMEM  (4*STAGEB)            // A[2] + B[2]

__global__ __launch_bounds__(256) void gemm_kernel(
    const __nv_bfloat16* __restrict__ A0, const __nv_bfloat16* __restrict__ A1, const __nv_bfloat16* __restrict__ A2,
    const __nv_bfloat16* __restrict__ B0, const __nv_bfloat16* __restrict__ B1, const __nv_bfloat16* __restrict__ B2,
    float* __restrict__ C)
{
    extern __shared__ __nv_bfloat16 sh[];
    uint32_t sbA = smem_u32(sh);
    uint32_t sbB = sbA + 2*STAGEB;

    const int tid = threadIdx.x, lane = tid & 31, w = tid >> 5;
    const int wm = w & 1, wn = w >> 1;
    const size_t m0 = (size_t)blockIdx.x * 128;
    const int n0 = blockIdx.y * 128;

    const __nv_bfloat16* Aarr[3] = {A0, A1, A2};
    const __nv_bfloat16* Barr[3] = {B0, B1, B2};
    const int PA[6] = {0, 0, 1, 1, 0, 2};
    const int PB[6] = {0, 1, 0, 1, 2, 0};

    float acc[4][4][4];
#pragma unroll
    for (int i = 0; i < 4; i++)
#pragma unroll
        for (int j = 0; j < 4; j++)
#pragma unroll
            for (int q = 0; q < 4; q++) acc[i][j][q] = 0.f;

    // per-thread copy coordinates (4 x 16B for A, 4 for B per stage)
    int crow[4], cseg[4];
#pragma unroll
    for (int i = 0; i < 4; i++){ int id = tid + i*256; crow[i] = id >> 3; cseg[i] = id & 7; }

    // fragment smem coordinates
    const int arow = wm*64 + (lane & 15);
    const int akof = (lane >> 4) * 8;
    const int brow = wn*32 + (lane & 7) + ((lane >> 4) << 3);
    const int bkof = ((lane >> 3) & 1) * 8;

    auto load_stage = [&](int s){
        int p = s >> 2, ch = s & 3, buf = s & 1;
        const __nv_bfloat16* Asrc = Aarr[PA[p]] + m0*256 + ch*64;
        const __nv_bfloat16* Bsrc = Barr[PB[p]] + (size_t)n0*256 + ch*64;
#pragma unroll
        for (int i = 0; i < 4; i++){
            uint32_t off = (uint32_t)(crow[i]*ASTR + cseg[i]*8) * 2 + buf*STAGEB;
            cpa16(sbA + off, Asrc + (size_t)crow[i]*256 + cseg[i]*8);
            cpa16(sbB + off, Bsrc + (size_t)crow[i]*256 + cseg[i]*8);
        }
        CP_COMMIT();
    };

    load_stage(0);
#pragma unroll 1
    for (int s = 0; s < 24; s++){
        if (s + 1 < 24){ load_stage(s + 1); CP_WAIT1(); }
        else CP_WAIT0();
        __syncthreads();
        uint32_t ab = sbA + (s & 1)*STAGEB;
        uint32_t bb = sbB + (s & 1)*STAGEB;
#pragma unroll
        for (int ks = 0; ks < 4; ks++){
            uint32_t a[4][4];
#pragma unroll
            for (int fm = 0; fm < 4; fm++)
                ldsm4(a[fm], ab + (uint32_t)((arow + fm*16)*ASTR + ks*16 + akof)*2);
            uint32_t b[4][2];
#pragma unroll
            for (int f2 = 0; f2 < 2; f2++){
                uint32_t r[4];
                ldsm4(r, bb + (uint32_t)((brow + f2*16)*ASTR + ks*16 + bkof)*2);
                b[f2*2][0] = r[0]; b[f2*2][1] = r[1];
                b[f2*2+1][0] = r[2]; b[f2*2+1][1] = r[3];
            }
#pragma unroll
            for (int fm = 0; fm < 4; fm++)
#pragma unroll
                for (int fn = 0; fn < 4; fn++)
                    mma16816(acc[fm][fn], a[fm], b[fn]);
        }
        __syncthreads();
    }

    // epilogue: c0,c1 -> (m = base+lane/4, n = 2*(lane%4)); c2,c3 -> m+8
#pragma unroll
    for (int fm = 0; fm < 4; fm++){
        size_t mrow = m0 + wm*64 + fm*16 + (lane >> 2);
        float* cp0 = C + mrow*NB       + n0 + wn*32 + 2*(lane & 3);
        float* cp1 = C + (mrow+8)*NB   + n0 + wn*32 + 2*(lane & 3);
#pragma unroll
        for (int fn = 0; fn < 4; fn++){
            *(float2*)(cp0 + fn*8) = make_float2(acc[fm][fn][0], acc[fm][fn][1]);
            *(float2*)(cp1 + fn*8) = make_float2(acc[fm][fn][2], acc[fm][fn][3]);
        }
    }
}

// ================= cell: gates_h (g_graw) + gathered gates_x -> h,c =================
__global__ __launch_bounds__(256) void cell_kernel(int step){
    int k = threadIdx.x;
#pragma unroll
    for (int rr = 0; rr < 4; rr++){
        int r = blockIdx.x*4 + rr;
        const float* g = g_graw + (size_t)r*NB;
        float gi = g[k], gf = g[256+k], gg = g[512+k], go = g[768+k];
        if (step > 0){
            int t = r / NPT, n = r % NPT;
            const float* ex = eih_ptr(t) + (size_t)(n*Ssz + g_idx[r])*NB;
            gi += ex[k]; gf += ex[256+k]; gg += ex[512+k]; go += ex[768+k];
        }
        float i = fsig (gi + g_bias[k]);
        float f = fsig (gf + g_bias[256+k]);
        float gv= ftanh(gg + g_bias[512+k]);
        float o = fsig (go + g_bias[768+k]);
        float cn = fmaf(f, g_c[r*256+k], i*gv);
        g_c[r*256+k] = cn;
        float h = o * ftanh(cn);
        split3(h, g_h0s[r*256+k], g_h1s[r*256+k], g_h2s[r*256+k]);
    }
}

// ================= attention: u = vt . tanh(enc_t + dec); softmax + argmax =================
__global__ __launch_bounds__(256) void attn_kernel(int step, const float* __restrict__ vt,
                                                   float* __restrict__ out){
    __shared__ float dec_s[256], vt_s[256], u_s[Ssz];
    int tid = threadIdx.x, wid = tid >> 5, lane = tid & 31;
    int r = blockIdx.x;                       // global row 0..9599
    int t = r / NPT, n = r % NPT;
    dec_s[tid] = g_graw[(size_t)r*NB + 1024 + tid];
    vt_s[tid]  = vt[tid];
    __syncthreads();

    const float* eb = eih_ptr(t) + (size_t)n*Ssz*NB + 1024;
#pragma unroll 1
    for (int s = wid; s < Ssz; s += 8){
        const float4* ep = (const float4*)(eb + (size_t)s*NB);
        float4 e0 = ep[lane], e1 = ep[32 + lane];
        float4 d0 = *(const float4*)(&dec_s[4*lane]);
        float4 d1 = *(const float4*)(&dec_s[128 + 4*lane]);
        float4 v0 = *(const float4*)(&vt_s[4*lane]);
        float4 v1 = *(const float4*)(&vt_s[128 + 4*lane]);
        float p0 = ftanh(e0.x + d0.x) * v0.x;
        float p1 = ftanh(e0.y + d0.y) * v0.y;
        p0 = fmaf(ftanh(e0.z + d0.z), v0.z, p0);
        p1 = fmaf(ftanh(e0.w + d0.w), v0.w, p1);
        p0 = fmaf(ftanh(e1.x + d1.x), v1.x, p0);
        p1 = fmaf(ftanh(e1.y + d1.y), v1.y, p1);
        p0 = fmaf(ftanh(e1.z + d1.z), v1.z, p0);
        p1 = fmaf(ftanh(e1.w + d1.w), v1.w, p1);
        float p = p0 + p1;
#pragma unroll
        for (int off = 16; off; off >>= 1) p += __shfl_xor_sync(0xffffffffu, p, off);
        if (lane == 0) u_s[s] = p;
    }
    __syncthreads();

    if (wid == 0){
        float ua = u_s[lane];
        float ub = (lane + 32 < Ssz) ? u_s[lane + 32] : -CUDART_INF_F;
        float bm = ua; int bi = lane;
        if (ub > bm){ bm = ub; bi = lane + 32; }
#pragma unroll
        for (int off = 16; off; off >>= 1){
            float vm = __shfl_xor_sync(0xffffffffu, bm, off);
            int   vi = __shfl_xor_sync(0xffffffffu, bi, off);
            if (vm > bm || (vm == bm && vi < bi)){ bm = vm; bi = vi; }
        }
        float ea = __expf(ua - bm);
        float eb2 = (lane + 32 < Ssz) ? __expf(ub - bm) : 0.f;
        float sm = ea + eb2;
#pragma unroll
        for (int off = 16; off; off >>= 1) sm += __shfl_xor_sync(0xffffffffu, sm, off);
        float inv = 1.0f / sm;
        float* so = out + (size_t)t*8160000 + (size_t)n*2500 + step*50;
        so[lane] = ea * inv;
        if (lane + 32 < Ssz) so[lane + 32] = eb2 * inv;
        if (lane == 0){
            g_idx[r] = bi;
            out[(size_t)t*8160000 + 8000000 + (size_t)n*50 + step] = (float)bi;
        }
    }
}

// ================= launch =================
extern "C" void kernel_launch(void* const* d_in, const int* in_sizes, int n_in,
                              void* d_out, int out_size){
    const float* home = (const float*)d_in[0];
    const float* vis  = (const float*)d_in[1];
    const float* team = (const float*)d_in[2];
    const float* Wih  = (const float*)d_in[3];
    const float* Whh  = (const float*)d_in[4];
    const float* bih  = (const float*)d_in[5];
    const float* bhh  = (const float*)d_in[6];
    const float* W1   = (const float*)d_in[7];
    const float* W2   = (const float*)d_in[8];
    const float* vt   = (const float*)d_in[9];
    float* out = (float*)d_out;

    cudaFuncSetAttribute(gemm_kernel, cudaFuncAttributeMaxDynamicSharedMemorySize, GSMEM);

    pack_b_kernel<<<NB, 256>>>(Whh, W2, Wih, W1, bih, bhh);
    split_enc_kernel<<<60000, 256>>>(home, vis, team);
    h0_kernel<<<NROW, 256>>>(home, vis, team);

    __nv_bfloat16 *es0, *es1, *es2, *bp0, *bp1, *bp2, *bs0, *bs1, *bs2, *h0, *h1, *h2;
    float *eih0, *eih1, *eih2, *graw;
    cudaGetSymbolAddress((void**)&es0, g_es0);  cudaGetSymbolAddress((void**)&es1, g_es1);
    cudaGetSymbolAddress((void**)&es2, g_es2);
    cudaGetSymbolAddress((void**)&bp0, g_bp0);  cudaGetSymbolAddress((void**)&bp1, g_bp1);
    cudaGetSymbolAddress((void**)&bp2, g_bp2);
    cudaGetSymbolAddress((void**)&bs0, g_bs0);  cudaGetSymbolAddress((void**)&bs1, g_bs1);
    cudaGetSymbolAddress((void**)&bs2, g_bs2);
    cudaGetSymbolAddress((void**)&h0,  g_h0s);  cudaGetSymbolAddress((void**)&h1,  g_h1s);
    cudaGetSymbolAddress((void**)&h2,  g_h2s);
    cudaGetSymbolAddress((void**)&eih0, g_eih0); cudaGetSymbolAddress((void**)&eih1, g_eih1);
    cudaGetSymbolAddress((void**)&eih2, g_eih2); cudaGetSymbolAddress((void**)&graw, g_graw);

    float* eihs[3] = {eih0, eih1, eih2};
    for (int t = 0; t < 3; t++){
        size_t off = (size_t)t * ERT * 256;
        gemm_kernel<<<dim3(1250, 10), 256, GSMEM>>>(es0 + off, es1 + off, es2 + off,
                                                    bp0, bp1, bp2, eihs[t]);
    }

    // bootstrap: gates_h(+dec) from h0
    gemm_kernel<<<dim3(75, 10), 256, GSMEM>>>(h0, h1, h2, bs0, bs1, bs2, graw);
    for (int i = 0; i < Ssz; i++){
        cell_kernel<<<NROW/4, 256>>>(i);
        gemm_kernel<<<dim3(75, 10), 256, GSMEM>>>(h0, h1, h2, bs0, bs1, bs2, graw);
        attn_kernel<<<NROW, 256>>>(i, vt, out);
    }
}

// round 6
// speedup vs baseline: 2.0679x; 1.4865x over previous
#include <cuda_runtime.h>
#include <cuda_fp16.h>
#include <math_constants.h>
#include <cstdint>

#define Ssz  50
#define NPT  3200
#define NROW 9600
#define ERT  160000
#define NB   1280

#define RSCALE   2048.0f          // residual scale 2^11
#define RINV     (1.0f/2048.0f)

// ================= static device scratch (no allocation) =================
static __device__ __half g_es0[(size_t)480000*256], g_es1[(size_t)480000*256];
static __device__ float g_eih0[(size_t)ERT*NB], g_eih1[(size_t)ERT*NB], g_eih2[(size_t)ERT*NB];
static __device__ __half g_h0s[NROW*256], g_h1s[NROW*256];
static __device__ float g_c[NROW*256];
static __device__ float g_graw[(size_t)NROW*NB];
static __device__ __half g_bs0[NB*256], g_bs1[NB*256];   // [Whh;W2] splits
static __device__ __half g_bp0[NB*256], g_bp1[NB*256];   // [Wih;W1] splits
static __device__ float g_bias[1024];
static __device__ int   g_idx[NROW];

__device__ __forceinline__ float* eih_ptr(int t){ return (t==0)?g_eih0:((t==1)?g_eih1:g_eih2); }
__device__ __forceinline__ void split2(float v, __half& a, __half& b){
    a = __float2half_rn(v);
    float r = v - __half2float(a);
    b = __float2half_rn(r * RSCALE);
}
__device__ __forceinline__ float fsig(float x){ return __fdividef(1.f, 1.f + __expf(-x)); }
__device__ __forceinline__ float ftanh(float x){ return 1.f - __fdividef(2.f, 1.f + __expf(2.f*x)); }

// ================= baseline-PTX tensor helpers =================
__device__ __forceinline__ uint32_t smem_u32(const void* p){
    uint32_t a;
    asm("{ .reg .u64 t; cvta.to.shared.u64 t, %1; cvt.u32.u64 %0, t; }" : "=r"(a) : "l"(p));
    return a;
}
__device__ __forceinline__ void ldsm4(uint32_t* r, uint32_t addr){
    asm volatile("ldmatrix.sync.aligned.m8n8.x4.shared.b16 {%0,%1,%2,%3}, [%4];"
        : "=r"(r[0]), "=r"(r[1]), "=r"(r[2]), "=r"(r[3]) : "r"(addr));
}
__device__ __forceinline__ void mma16816(float* c, const uint32_t* a, const uint32_t* b){
    asm volatile("mma.sync.aligned.m16n8k16.row.col.f32.f16.f16.f32 "
        "{%0,%1,%2,%3}, {%4,%5,%6,%7}, {%8,%9}, {%0,%1,%2,%3};"
        : "+f"(c[0]), "+f"(c[1]), "+f"(c[2]), "+f"(c[3])
        : "r"(a[0]), "r"(a[1]), "r"(a[2]), "r"(a[3]), "r"(b[0]), "r"(b[1]));
}
__device__ __forceinline__ void cpa16(uint32_t d, const void* s){
    asm volatile("cp.async.cg.shared.global [%0], [%1], 16;" :: "r"(d), "l"(s));
}
#define CP_COMMIT() asm volatile("cp.async.commit_group;" ::: "memory")
#define CP_WAIT0()  asm volatile("cp.async.wait_group 0;" ::: "memory")
#define CP_WAIT1()  asm volatile("cp.async.wait_group 1;" ::: "memory")

// ================= prep kernels =================
__global__ void pack_b_kernel(const float* __restrict__ Whh, const float* __restrict__ W2,
                              const float* __restrict__ Wih, const float* __restrict__ W1,
                              const float* __restrict__ bih, const float* __restrict__ bhh){
    int row = blockIdx.x, k = threadIdx.x, j = row*256 + k;
    float ws = (row < 1024) ? Whh[j] : W2[(size_t)(row-1024)*256 + k];
    float wp = (row < 1024) ? Wih[j] : W1[(size_t)(row-1024)*256 + k];
    split2(ws, g_bs0[j], g_bs1[j]);
    split2(wp, g_bp0[j], g_bp1[j]);
    if (row < 4) g_bias[j] = bih[j] + bhh[j];
}

__global__ void split_enc_kernel(const float* __restrict__ e0, const float* __restrict__ e1,
                                 const float* __restrict__ e2){
    int k = threadIdx.x;
#pragma unroll
    for (int rr = 0; rr < 8; rr++){
        size_t R = (size_t)blockIdx.x*8 + rr;          // 0..479999
        int t = (int)(R / ERT);
        const float* e = (t==0)?e0:((t==1)?e1:e2);
        float v = e[(R - (size_t)t*ERT)*256 + k];
        split2(v, g_es0[R*256+k], g_es1[R*256+k]);
    }
}

__global__ void h0_kernel(const float* __restrict__ e0, const float* __restrict__ e1,
                          const float* __restrict__ e2){
    int r = blockIdx.x, k = threadIdx.x;
    int t = r / NPT, n = r % NPT;
    const float* e = ((t==0)?e0:((t==1)?e1:e2)) + (size_t)n*(Ssz*256) + k;
    float s = 0.f;
#pragma unroll 1
    for (int ss = 0; ss < Ssz; ss++) s += e[ss*256];
    g_c[r*256+k] = s;
    split2(s, g_h0s[r*256+k], g_h1s[r*256+k]);
}

// ================= emulated-fp32 GEMM via mma.sync fp16 (2-way split, 3 products) =================
// C = (A0 + A1/2048) @ (B0 + B1/2048)^T  ≈ A@B^T with ~2^-22 input error.
// acc0 += A0B0 ; acc1 += A0B1 + A1B0 ; C = acc0 + acc1/2048.
#define ASTR   72                     // smem row stride (halfs): 144B, conflict-free ldmatrix
#define TILEB  (128*ASTR*2)           // 18432 B per [128x64] tile
#define STAGE  (4*TILEB)              // A0,A1,B0,B1
#define GSMEM  (2*STAGE)              // double buffer = 147456 B

__global__ __launch_bounds__(256) void gemm_kernel(
    const __half* __restrict__ A0, const __half* __restrict__ A1,
    const __half* __restrict__ B0, const __half* __restrict__ B1,
    float* __restrict__ C)
{
    extern __shared__ __half sh[];
    uint32_t sb = smem_u32(sh);

    const int tid = threadIdx.x, lane = tid & 31, w = tid >> 5;
    const int wm = w & 1, wn = w >> 1;
    const size_t m0 = (size_t)blockIdx.x * 128;
    const int n0 = blockIdx.y * 128;

    float acc0[4][4][4], acc1[4][4][4];
#pragma unroll
    for (int i = 0; i < 4; i++)
#pragma unroll
        for (int j = 0; j < 4; j++)
#pragma unroll
            for (int q = 0; q < 4; q++){ acc0[i][j][q] = 0.f; acc1[i][j][q] = 0.f; }

    const __half* tsrc[4] = { A0 + m0*256, A1 + m0*256,
                              B0 + (size_t)n0*256, B1 + (size_t)n0*256 };

    int crow[4], cseg[4];
#pragma unroll
    for (int i = 0; i < 4; i++){ int id = tid + i*256; crow[i] = id >> 3; cseg[i] = id & 7; }

    const int arow = wm*64 + (lane & 15);
    const int akof = (lane >> 4) * 8;
    const int brow = wn*32 + (lane & 7) + ((lane >> 4) << 3);
    const int bkof = ((lane >> 3) & 1) * 8;

    auto load_stage = [&](int c){
        uint32_t base = sb + (uint32_t)(c & 1)*STAGE;
#pragma unroll
        for (int t = 0; t < 4; t++){
            const __half* src = tsrc[t] + c*64;
#pragma unroll
            for (int i = 0; i < 4; i++){
                uint32_t off = (uint32_t)(crow[i]*ASTR + cseg[i]*8)*2 + t*TILEB;
                cpa16(base + off, src + (size_t)crow[i]*256 + cseg[i]*8);
            }
        }
        CP_COMMIT();
    };

    load_stage(0);
#pragma unroll 1
    for (int c = 0; c < 4; c++){
        if (c + 1 < 4){ load_stage(c + 1); CP_WAIT1(); }
        else CP_WAIT0();
        __syncthreads();
        uint32_t base = sb + (uint32_t)(c & 1)*STAGE;
        uint32_t a0b = base, a1b = base + TILEB, b0b = base + 2*TILEB, b1b = base + 3*TILEB;
#pragma unroll
        for (int ks = 0; ks < 4; ks++){
            // B fragments: b0f/b1f for 4 fn each
            uint32_t b0f[4][2], b1f[4][2];
#pragma unroll
            for (int f2 = 0; f2 < 2; f2++){
                uint32_t off = (uint32_t)((brow + f2*16)*ASTR + ks*16 + bkof)*2;
                uint32_t r[4];
                ldsm4(r, b0b + off);
                b0f[f2*2][0] = r[0]; b0f[f2*2][1] = r[1];
                b0f[f2*2+1][0] = r[2]; b0f[f2*2+1][1] = r[3];
                ldsm4(r, b1b + off);
                b1f[f2*2][0] = r[0]; b1f[f2*2][1] = r[1];
                b1f[f2*2+1][0] = r[2]; b1f[f2*2+1][1] = r[3];
            }
#pragma unroll
            for (int fm = 0; fm < 4; fm++){
                uint32_t aoff = (uint32_t)((arow + fm*16)*ASTR + ks*16 + akof)*2;
                uint32_t a0f[4], a1f[4];
                ldsm4(a0f, a0b + aoff);
                ldsm4(a1f, a1b + aoff);
#pragma unroll
                for (int fn = 0; fn < 4; fn++){
                    mma16816(acc0[fm][fn], a0f, b0f[fn]);
                    mma16816(acc1[fm][fn], a0f, b1f[fn]);
                    mma16816(acc1[fm][fn], a1f, b0f[fn]);
                }
            }
        }
        __syncthreads();
    }

    // epilogue
#pragma unroll
    for (int fm = 0; fm < 4; fm++){
        size_t mrow = m0 + wm*64 + fm*16 + (lane >> 2);
        float* cp0 = C + mrow*NB     + n0 + wn*32 + 2*(lane & 3);
        float* cp1 = C + (mrow+8)*NB + n0 + wn*32 + 2*(lane & 3);
#pragma unroll
        for (int fn = 0; fn < 4; fn++){
            *(float2*)(cp0 + fn*8) = make_float2(fmaf(acc1[fm][fn][0], RINV, acc0[fm][fn][0]),
                                                 fmaf(acc1[fm][fn][1], RINV, acc0[fm][fn][1]));
            *(float2*)(cp1 + fn*8) = make_float2(fmaf(acc1[fm][fn][2], RINV, acc0[fm][fn][2]),
                                                 fmaf(acc1[fm][fn][3], RINV, acc0[fm][fn][3]));
        }
    }
}

// ================= cell: gates_h (g_graw) + gathered gates_x -> h,c =================
__global__ __launch_bounds__(256) void cell_kernel(int step){
    int k = threadIdx.x;
#pragma unroll
    for (int rr = 0; rr < 4; rr++){
        int r = blockIdx.x*4 + rr;
        const float* g = g_graw + (size_t)r*NB;
        float gi = g[k], gf = g[256+k], gg = g[512+k], go = g[768+k];
        if (step > 0){
            int t = r / NPT, n = r % NPT;
            const float* ex = eih_ptr(t) + (size_t)(n*Ssz + g_idx[r])*NB;
            gi += ex[k]; gf += ex[256+k]; gg += ex[512+k]; go += ex[768+k];
        }
        float i = fsig (gi + g_bias[k]);
        float f = fsig (gf + g_bias[256+k]);
        float gv= ftanh(gg + g_bias[512+k]);
        float o = fsig (go + g_bias[768+k]);
        float cn = fmaf(f, g_c[r*256+k], i*gv);
        g_c[r*256+k] = cn;
        float h = o * ftanh(cn);
        split2(h, g_h0s[r*256+k], g_h1s[r*256+k]);
    }
}

// ================= attention: u = vt . tanh(enc_t + dec); softmax + argmax =================
__global__ __launch_bounds__(256) void attn_kernel(int step, const float* __restrict__ vt,
                                                   float* __restrict__ out){
    __shared__ float dec_s[256], vt_s[256], u_s[Ssz];
    int tid = threadIdx.x, wid = tid >> 5, lane = tid & 31;
    int r = blockIdx.x;                       // global row 0..9599
    int t = r / NPT, n = r % NPT;
    dec_s[tid] = g_graw[(size_t)r*NB + 1024 + tid];
    vt_s[tid]  = vt[tid];
    __syncthreads();

    const float* eb = eih_ptr(t) + (size_t)n*Ssz*NB + 1024;
#pragma unroll 1
    for (int s = wid; s < Ssz; s += 8){
        const float4* ep = (const float4*)(eb + (size_t)s*NB);
        float4 e0 = ep[lane], e1 = ep[32 + lane];
        float4 d0 = *(const float4*)(&dec_s[4*lane]);
        float4 d1 = *(const float4*)(&dec_s[128 + 4*lane]);
        float4 v0 = *(const float4*)(&vt_s[4*lane]);
        float4 v1 = *(const float4*)(&vt_s[128 + 4*lane]);
        float p0 = ftanh(e0.x + d0.x) * v0.x;
        float p1 = ftanh(e0.y + d0.y) * v0.y;
        p0 = fmaf(ftanh(e0.z + d0.z), v0.z, p0);
        p1 = fmaf(ftanh(e0.w + d0.w), v0.w, p1);
        p0 = fmaf(ftanh(e1.x + d1.x), v1.x, p0);
        p1 = fmaf(ftanh(e1.y + d1.y), v1.y, p1);
        p0 = fmaf(ftanh(e1.z + d1.z), v1.z, p0);
        p1 = fmaf(ftanh(e1.w + d1.w), v1.w, p1);
        float p = p0 + p1;
#pragma unroll
        for (int off = 16; off; off >>= 1) p += __shfl_xor_sync(0xffffffffu, p, off);
        if (lane == 0) u_s[s] = p;
    }
    __syncthreads();

    if (wid == 0){
        float ua = u_s[lane];
        float ub = (lane + 32 < Ssz) ? u_s[lane + 32] : -CUDART_INF_F;
        float bm = ua; int bi = lane;
        if (ub > bm){ bm = ub; bi = lane + 32; }
#pragma unroll
        for (int off = 16; off; off >>= 1){
            float vm = __shfl_xor_sync(0xffffffffu, bm, off);
            int   vi = __shfl_xor_sync(0xffffffffu, bi, off);
            if (vm > bm || (vm == bm && vi < bi)){ bm = vm; bi = vi; }
        }
        float ea = __expf(ua - bm);
        float eb2 = (lane + 32 < Ssz) ? __expf(ub - bm) : 0.f;
        float sm = ea + eb2;
#pragma unroll
        for (int off = 16; off; off >>= 1) sm += __shfl_xor_sync(0xffffffffu, sm, off);
        float inv = 1.0f / sm;
        float* so = out + (size_t)t*8160000 + (size_t)n*2500 + step*50;
        so[lane] = ea * inv;
        if (lane + 32 < Ssz) so[lane + 32] = eb2 * inv;
        if (lane == 0){
            g_idx[r] = bi;
            out[(size_t)t*8160000 + 8000000 + (size_t)n*50 + step] = (float)bi;
        }
    }
}

// ================= launch =================
extern "C" void kernel_launch(void* const* d_in, const int* in_sizes, int n_in,
                              void* d_out, int out_size){
    const float* home = (const float*)d_in[0];
    const float* vis  = (const float*)d_in[1];
    const float* team = (const float*)d_in[2];
    const float* Wih  = (const float*)d_in[3];
    const float* Whh  = (const float*)d_in[4];
    const float* bih  = (const float*)d_in[5];
    const float* bhh  = (const float*)d_in[6];
    const float* W1   = (const float*)d_in[7];
    const float* W2   = (const float*)d_in[8];
    const float* vt   = (const float*)d_in[9];
    float* out = (float*)d_out;

    cudaFuncSetAttribute(gemm_kernel, cudaFuncAttributeMaxDynamicSharedMemorySize, GSMEM);

    pack_b_kernel<<<NB, 256>>>(Whh, W2, Wih, W1, bih, bhh);
    split_enc_kernel<<<60000, 256>>>(home, vis, team);
    h0_kernel<<<NROW, 256>>>(home, vis, team);

    __half *es0, *es1, *bp0, *bp1, *bs0, *bs1, *h0, *h1;
    float *eih0, *eih1, *eih2, *graw;
    cudaGetSymbolAddress((void**)&es0, g_es0);  cudaGetSymbolAddress((void**)&es1, g_es1);
    cudaGetSymbolAddress((void**)&bp0, g_bp0);  cudaGetSymbolAddress((void**)&bp1, g_bp1);
    cudaGetSymbolAddress((void**)&bs0, g_bs0);  cudaGetSymbolAddress((void**)&bs1, g_bs1);
    cudaGetSymbolAddress((void**)&h0,  g_h0s);  cudaGetSymbolAddress((void**)&h1,  g_h1s);
    cudaGetSymbolAddress((void**)&eih0, g_eih0); cudaGetSymbolAddress((void**)&eih1, g_eih1);
    cudaGetSymbolAddress((void**)&eih2, g_eih2); cudaGetSymbolAddress((void**)&graw, g_graw);

    float* eihs[3] = {eih0, eih1, eih2};
    for (int t = 0; t < 3; t++){
        size_t off = (size_t)t * ERT * 256;
        gemm_kernel<<<dim3(1250, 10), 256, GSMEM>>>(es0 + off, es1 + off, bp0, bp1, eihs[t]);
    }

    // bootstrap: gates_h(+dec) from h0
    gemm_kernel<<<dim3(75, 10), 256, GSMEM>>>(h0, h1, bs0, bs1, graw);
    for (int i = 0; i < Ssz; i++){
        cell_kernel<<<NROW/4, 256>>>(i);
        gemm_kernel<<<dim3(75, 10), 256, GSMEM>>>(h0, h1, bs0, bs1, graw);
        attn_kernel<<<NROW, 256>>>(i, vt, out);
    }
}

// round 7
// speedup vs baseline: 2.0744x; 1.0031x over previous
#include <cuda_runtime.h>
#include <cuda_fp16.h>
#include <math_constants.h>
#include <cstdint>

#define Ssz  50
#define NPT  3200
#define NROW 9600
#define ERT  160000
#define NB   1280

#define RSCALE   2048.0f          // residual scale 2^11
#define RINV     (1.0f/2048.0f)

// ================= static device scratch (no allocation) =================
static __device__ __half g_es0[(size_t)480000*256], g_es1[(size_t)480000*256];
static __device__ float g_eih0[(size_t)ERT*NB], g_eih1[(size_t)ERT*NB], g_eih2[(size_t)ERT*NB];
static __device__ __half g_h0s[NROW*256], g_h1s[NROW*256];
static __device__ float g_c[NROW*256];
static __device__ float g_graw[(size_t)NROW*NB];
static __device__ __half g_bs0[NB*256], g_bs1[NB*256];   // [Whh;W2] splits
static __device__ __half g_bp0[NB*256], g_bp1[NB*256];   // [Wih;W1] splits
static __device__ float g_bias[1024];

__device__ __forceinline__ float* eih_ptr(int t){ return (t==0)?g_eih0:((t==1)?g_eih1:g_eih2); }
__device__ __forceinline__ void split2(float v, __half& a, __half& b){
    a = __float2half_rn(v);
    float r = v - __half2float(a);
    b = __float2half_rn(r * RSCALE);
}
__device__ __forceinline__ float fsig(float x){ return __fdividef(1.f, 1.f + __expf(-x)); }
__device__ __forceinline__ float ftanh(float x){ return 1.f - __fdividef(2.f, 1.f + __expf(2.f*x)); }

// ================= baseline-PTX tensor helpers =================
__device__ __forceinline__ uint32_t smem_u32(const void* p){
    uint32_t a;
    asm("{ .reg .u64 t; cvta.to.shared.u64 t, %1; cvt.u32.u64 %0, t; }" : "=r"(a) : "l"(p));
    return a;
}
__device__ __forceinline__ void ldsm4(uint32_t* r, uint32_t addr){
    asm volatile("ldmatrix.sync.aligned.m8n8.x4.shared.b16 {%0,%1,%2,%3}, [%4];"
        : "=r"(r[0]), "=r"(r[1]), "=r"(r[2]), "=r"(r[3]) : "r"(addr));
}
__device__ __forceinline__ void mma16816(float* c, const uint32_t* a, const uint32_t* b){
    asm volatile("mma.sync.aligned.m16n8k16.row.col.f32.f16.f16.f32 "
        "{%0,%1,%2,%3}, {%4,%5,%6,%7}, {%8,%9}, {%0,%1,%2,%3};"
        : "+f"(c[0]), "+f"(c[1]), "+f"(c[2]), "+f"(c[3])
        : "r"(a[0]), "r"(a[1]), "r"(a[2]), "r"(a[3]), "r"(b[0]), "r"(b[1]));
}
__device__ __forceinline__ void cpa16(uint32_t d, const void* s){
    asm volatile("cp.async.cg.shared.global [%0], [%1], 16;" :: "r"(d), "l"(s));
}
#define CP_COMMIT() asm volatile("cp.async.commit_group;" ::: "memory")
#define CP_WAIT0()  asm volatile("cp.async.wait_group 0;" ::: "memory")
#define CP_WAIT1()  asm volatile("cp.async.wait_group 1;" ::: "memory")

// ================= prep kernels =================
__global__ void pack_b_kernel(const float* __restrict__ Whh, const float* __restrict__ W2,
                              const float* __restrict__ Wih, const float* __restrict__ W1,
                              const float* __restrict__ bih, const float* __restrict__ bhh){
    int row = blockIdx.x, k = threadIdx.x, j = row*256 + k;
    float ws = (row < 1024) ? Whh[j] : W2[(size_t)(row-1024)*256 + k];
    float wp = (row < 1024) ? Wih[j] : W1[(size_t)(row-1024)*256 + k];
    split2(ws, g_bs0[j], g_bs1[j]);
    split2(wp, g_bp0[j], g_bp1[j]);
    if (row < 4) g_bias[j] = bih[j] + bhh[j];
}

__global__ void split_enc_kernel(const float* __restrict__ e0, const float* __restrict__ e1,
                                 const float* __restrict__ e2){
    int k = threadIdx.x;
#pragma unroll
    for (int rr = 0; rr < 8; rr++){
        size_t R = (size_t)blockIdx.x*8 + rr;          // 0..479999
        int t = (int)(R / ERT);
        const float* e = (t==0)?e0:((t==1)?e1:e2);
        float v = e[(R - (size_t)t*ERT)*256 + k];
        split2(v, g_es0[R*256+k], g_es1[R*256+k]);
    }
}

__global__ void h0_kernel(const float* __restrict__ e0, const float* __restrict__ e1,
                          const float* __restrict__ e2){
    int r = blockIdx.x, k = threadIdx.x;
    int t = r / NPT, n = r % NPT;
    const float* e = ((t==0)?e0:((t==1)?e1:e2)) + (size_t)n*(Ssz*256) + k;
    float s = 0.f;
#pragma unroll 1
    for (int ss = 0; ss < Ssz; ss++) s += e[ss*256];
    g_c[r*256+k] = s;
    split2(s, g_h0s[r*256+k], g_h1s[r*256+k]);
}

// ================= emulated-fp32 GEMM via mma.sync fp16 (2-way split, 3 products) =================
// CTA tile 128x64, warp tile 32x32 (4x2 warps), 2 CTAs/SM.
#define ASTR   72
#define ATILE  (128*ASTR*2)           // 18432 B
#define BTILE  (64*ASTR*2)            // 9216 B
#define STAGE  (2*ATILE + 2*BTILE)    // 55296 B : A0 A1 B0 B1
#define GSMEM  (2*STAGE)              // 110592 B

__global__ __launch_bounds__(256, 2) void gemm_kernel(
    const __half* __restrict__ A0, const __half* __restrict__ A1,
    const __half* __restrict__ B0, const __half* __restrict__ B1,
    float* __restrict__ C)
{
    extern __shared__ __half sh[];
    uint32_t sb = smem_u32(sh);

    const int tid = threadIdx.x, lane = tid & 31, w = tid >> 5;
    const int wm = w & 3, wn = w >> 2;
    const size_t m0 = (size_t)blockIdx.x * 128;
    const int n0 = blockIdx.y * 64;

    float acc0[2][4][4], acc1[2][4][4];
#pragma unroll
    for (int i = 0; i < 2; i++)
#pragma unroll
        for (int j = 0; j < 4; j++)
#pragma unroll
            for (int q = 0; q < 4; q++){ acc0[i][j][q] = 0.f; acc1[i][j][q] = 0.f; }

    const __half* Asrc[2] = { A0 + m0*256, A1 + m0*256 };
    const __half* Bsrc[2] = { B0 + (size_t)n0*256, B1 + (size_t)n0*256 };

    const int arow = wm*32 + (lane & 15);
    const int akof = (lane >> 4) * 8;
    const int brow = wn*32 + (lane & 7) + ((lane >> 4) << 3);
    const int bkof = ((lane >> 3) & 1) * 8;

    auto load_stage = [&](int c){
        uint32_t base = sb + (uint32_t)(c & 1)*STAGE;
#pragma unroll
        for (int t = 0; t < 2; t++){
            const __half* src = Asrc[t] + c*64;
#pragma unroll
            for (int i = 0; i < 4; i++){
                int id = tid + i*256, row = id >> 3, seg = id & 7;
                cpa16(base + t*ATILE + (uint32_t)(row*ASTR + seg*8)*2,
                      src + (size_t)row*256 + seg*8);
            }
        }
#pragma unroll
        for (int t = 0; t < 2; t++){
            const __half* src = Bsrc[t] + c*64;
#pragma unroll
            for (int i = 0; i < 2; i++){
                int id = tid + i*256, row = id >> 3, seg = id & 7;
                cpa16(base + 2*ATILE + t*BTILE + (uint32_t)(row*ASTR + seg*8)*2,
                      src + (size_t)row*256 + seg*8);
            }
        }
        CP_COMMIT();
    };

    load_stage(0);
#pragma unroll 1
    for (int c = 0; c < 4; c++){
        if (c + 1 < 4){ load_stage(c + 1); CP_WAIT1(); }
        else CP_WAIT0();
        __syncthreads();
        uint32_t base = sb + (uint32_t)(c & 1)*STAGE;
        uint32_t a0b = base, a1b = base + ATILE;
        uint32_t b0b = base + 2*ATILE, b1b = b0b + BTILE;
#pragma unroll
        for (int ks = 0; ks < 4; ks++){
            uint32_t b0f[4][2], b1f[4][2];
#pragma unroll
            for (int f2 = 0; f2 < 2; f2++){
                uint32_t off = (uint32_t)((brow + f2*16)*ASTR + ks*16 + bkof)*2;
                uint32_t r[4];
                ldsm4(r, b0b + off);
                b0f[f2*2][0] = r[0]; b0f[f2*2][1] = r[1];
                b0f[f2*2+1][0] = r[2]; b0f[f2*2+1][1] = r[3];
                ldsm4(r, b1b + off);
                b1f[f2*2][0] = r[0]; b1f[f2*2][1] = r[1];
                b1f[f2*2+1][0] = r[2]; b1f[f2*2+1][1] = r[3];
            }
#pragma unroll
            for (int fm = 0; fm < 2; fm++){
                uint32_t aoff = (uint32_t)((arow + fm*16)*ASTR + ks*16 + akof)*2;
                uint32_t a0f[4], a1f[4];
                ldsm4(a0f, a0b + aoff);
                ldsm4(a1f, a1b + aoff);
#pragma unroll
                for (int fn = 0; fn < 4; fn++){
                    mma16816(acc0[fm][fn], a0f, b0f[fn]);
                    mma16816(acc1[fm][fn], a0f, b1f[fn]);
                    mma16816(acc1[fm][fn], a1f, b0f[fn]);
                }
            }
        }
        __syncthreads();
    }

    // epilogue
#pragma unroll
    for (int fm = 0; fm < 2; fm++){
        size_t mrow = m0 + wm*32 + fm*16 + (lane >> 2);
        float* cp0 = C + mrow*NB     + n0 + wn*32 + 2*(lane & 3);
        float* cp1 = C + (mrow+8)*NB + n0 + wn*32 + 2*(lane & 3);
#pragma unroll
        for (int fn = 0; fn < 4; fn++){
            *(float2*)(cp0 + fn*8) = make_float2(fmaf(acc1[fm][fn][0], RINV, acc0[fm][fn][0]),
                                                 fmaf(acc1[fm][fn][1], RINV, acc0[fm][fn][1]));
            *(float2*)(cp1 + fn*8) = make_float2(fmaf(acc1[fm][fn][2], RINV, acc0[fm][fn][2]),
                                                 fmaf(acc1[fm][fn][3], RINV, acc0[fm][fn][3]));
        }
    }
}

// ================= cell0: initial cell (x=0, no gather) =================
__global__ __launch_bounds__(256) void cell0_kernel(){
    int k = threadIdx.x;
#pragma unroll
    for (int rr = 0; rr < 4; rr++){
        int r = blockIdx.x*4 + rr;
        const float* g = g_graw + (size_t)r*NB;
        float i = fsig (g[k]     + g_bias[k]);
        float f = fsig (g[256+k] + g_bias[256+k]);
        float gv= ftanh(g[512+k] + g_bias[512+k]);
        float o = fsig (g[768+k] + g_bias[768+k]);
        float cn = fmaf(f, g_c[r*256+k], i*gv);
        g_c[r*256+k] = cn;
        split2(o * ftanh(cn), g_h0s[r*256+k], g_h1s[r*256+k]);
    }
}

// ================= fused attention(step) + cell(step+1) =================
__global__ __launch_bounds__(256) void attn_cell_kernel(int step, int do_cell,
                                                        const float* __restrict__ vt,
                                                        float* __restrict__ out){
    __shared__ float dec_s[256], vt_s[256], u_s[Ssz];
    __shared__ int idx_sh;
    int tid = threadIdx.x, wid = tid >> 5, lane = tid & 31;
    int r = blockIdx.x;                       // global row 0..9599
    int t = r / NPT, n = r % NPT;
    dec_s[tid] = g_graw[(size_t)r*NB + 1024 + tid];
    vt_s[tid]  = vt[tid];
    __syncthreads();

    const float* eb = eih_ptr(t) + (size_t)n*Ssz*NB + 1024;
#pragma unroll 1
    for (int s = wid; s < Ssz; s += 8){
        const float4* ep = (const float4*)(eb + (size_t)s*NB);
        float4 e0 = ep[lane], e1 = ep[32 + lane];
        float4 d0 = *(const float4*)(&dec_s[4*lane]);
        float4 d1 = *(const float4*)(&dec_s[128 + 4*lane]);
        float4 v0 = *(const float4*)(&vt_s[4*lane]);
        float4 v1 = *(const float4*)(&vt_s[128 + 4*lane]);
        float p0 = ftanh(e0.x + d0.x) * v0.x;
        float p1 = ftanh(e0.y + d0.y) * v0.y;
        p0 = fmaf(ftanh(e0.z + d0.z), v0.z, p0);
        p1 = fmaf(ftanh(e0.w + d0.w), v0.w, p1);
        p0 = fmaf(ftanh(e1.x + d1.x), v1.x, p0);
        p1 = fmaf(ftanh(e1.y + d1.y), v1.y, p1);
        p0 = fmaf(ftanh(e1.z + d1.z), v1.z, p0);
        p1 = fmaf(ftanh(e1.w + d1.w), v1.w, p1);
        float p = p0 + p1;
#pragma unroll
        for (int off = 16; off; off >>= 1) p += __shfl_xor_sync(0xffffffffu, p, off);
        if (lane == 0) u_s[s] = p;
    }
    __syncthreads();

    if (wid == 0){
        float ua = u_s[lane];
        float ub = (lane + 32 < Ssz) ? u_s[lane + 32] : -CUDART_INF_F;
        float bm = ua; int bi = lane;
        if (ub > bm){ bm = ub; bi = lane + 32; }
#pragma unroll
        for (int off = 16; off; off >>= 1){
            float vm = __shfl_xor_sync(0xffffffffu, bm, off);
            int   vi = __shfl_xor_sync(0xffffffffu, bi, off);
            if (vm > bm || (vm == bm && vi < bi)){ bm = vm; bi = vi; }
        }
        float ea = __expf(ua - bm);
        float eb2 = (lane + 32 < Ssz) ? __expf(ub - bm) : 0.f;
        float sm = ea + eb2;
#pragma unroll
        for (int off = 16; off; off >>= 1) sm += __shfl_xor_sync(0xffffffffu, sm, off);
        float inv = 1.0f / sm;
        float* so = out + (size_t)t*8160000 + (size_t)n*2500 + step*50;
        so[lane] = ea * inv;
        if (lane + 32 < Ssz) so[lane + 32] = eb2 * inv;
        if (lane == 0){
            idx_sh = bi;
            out[(size_t)t*8160000 + 8000000 + (size_t)n*50 + step] = (float)bi;
        }
    }
    __syncthreads();

    if (do_cell){
        int k = tid;
        const float* g = g_graw + (size_t)r*NB;
        const float* ex = eih_ptr(t) + (size_t)(n*Ssz + idx_sh)*NB;
        float i = fsig (g[k]     + ex[k]     + g_bias[k]);
        float f = fsig (g[256+k] + ex[256+k] + g_bias[256+k]);
        float gv= ftanh(g[512+k] + ex[512+k] + g_bias[512+k]);
        float o = fsig (g[768+k] + ex[768+k] + g_bias[768+k]);
        float cn = fmaf(f, g_c[r*256+k], i*gv);
        g_c[r*256+k] = cn;
        split2(o * ftanh(cn), g_h0s[r*256+k], g_h1s[r*256+k]);
    }
}

// ================= launch =================
extern "C" void kernel_launch(void* const* d_in, const int* in_sizes, int n_in,
                              void* d_out, int out_size){
    const float* home = (const float*)d_in[0];
    const float* vis  = (const float*)d_in[1];
    const float* team = (const float*)d_in[2];
    const float* Wih  = (const float*)d_in[3];
    const float* Whh  = (const float*)d_in[4];
    const float* bih  = (const float*)d_in[5];
    const float* bhh  = (const float*)d_in[6];
    const float* W1   = (const float*)d_in[7];
    const float* W2   = (const float*)d_in[8];
    const float* vt   = (const float*)d_in[9];
    float* out = (float*)d_out;

    cudaFuncSetAttribute(gemm_kernel, cudaFuncAttributeMaxDynamicSharedMemorySize, GSMEM);

    pack_b_kernel<<<NB, 256>>>(Whh, W2, Wih, W1, bih, bhh);
    split_enc_kernel<<<60000, 256>>>(home, vis, team);
    h0_kernel<<<NROW, 256>>>(home, vis, team);

    __half *es0, *es1, *bp0, *bp1, *bs0, *bs1, *h0, *h1;
    float *eih0, *eih1, *eih2, *graw;
    cudaGetSymbolAddress((void**)&es0, g_es0);  cudaGetSymbolAddress((void**)&es1, g_es1);
    cudaGetSymbolAddress((void**)&bp0, g_bp0);  cudaGetSymbolAddress((void**)&bp1, g_bp1);
    cudaGetSymbolAddress((void**)&bs0, g_bs0);  cudaGetSymbolAddress((void**)&bs1, g_bs1);
    cudaGetSymbolAddress((void**)&h0,  g_h0s);  cudaGetSymbolAddress((void**)&h1,  g_h1s);
    cudaGetSymbolAddress((void**)&eih0, g_eih0); cudaGetSymbolAddress((void**)&eih1, g_eih1);
    cudaGetSymbolAddress((void**)&eih2, g_eih2); cudaGetSymbolAddress((void**)&graw, g_graw);

    float* eihs[3] = {eih0, eih1, eih2};
    for (int t = 0; t < 3; t++){
        size_t off = (size_t)t * ERT * 256;
        gemm_kernel<<<dim3(1250, 20), 256, GSMEM>>>(es0 + off, es1 + off, bp0, bp1, eihs[t]);
    }

    // bootstrap: gates from h0 -> cell0 -> gates+dec
    gemm_kernel<<<dim3(75, 20), 256, GSMEM>>>(h0, h1, bs0, bs1, graw);
    cell0_kernel<<<NROW/4, 256>>>();
    gemm_kernel<<<dim3(75, 20), 256, GSMEM>>>(h0, h1, bs0, bs1, graw);

    for (int i = 0; i < Ssz; i++){
        attn_cell_kernel<<<NROW, 256>>>(i, (i + 1 < Ssz) ? 1 : 0, vt, out);
        if (i + 1 < Ssz)
            gemm_kernel<<<dim3(75, 20), 256, GSMEM>>>(h0, h1, bs0, bs1, graw);
    }
}

// round 8
// speedup vs baseline: 2.0996x; 1.0121x over previous
#include <cuda_runtime.h>
#include <cuda_fp16.h>
#include <math_constants.h>
#include <cstdint>

#define Ssz  50
#define NPT  3200
#define NROW 9600
#define ERT  160000
#define NB   1280

#define RSCALE   2048.0f          // residual scale 2^11
#define RINV     (1.0f/2048.0f)

// ================= static device scratch (no allocation) =================
static __device__ __half g_es0[(size_t)480000*256], g_es1[(size_t)480000*256];
static __device__ float g_gx0[(size_t)ERT*1024], g_gx1[(size_t)ERT*1024], g_gx2[(size_t)ERT*1024];
static __device__ float g_et0[(size_t)ERT*256],  g_et1[(size_t)ERT*256],  g_et2[(size_t)ERT*256];
static __device__ __half g_h0s[NROW*256], g_h1s[NROW*256];
static __device__ float g_c[NROW*256];
static __device__ float g_graw[(size_t)NROW*1024];
static __device__ float g_dec[(size_t)NROW*256];
static __device__ __half g_bs0[NB*256], g_bs1[NB*256];   // [Whh;W2] splits
static __device__ __half g_bp0[NB*256], g_bp1[NB*256];   // [Wih;W1] splits
static __device__ float g_bias[1024];

__device__ __forceinline__ float* gx_ptr(int t){ return (t==0)?g_gx0:((t==1)?g_gx1:g_gx2); }
__device__ __forceinline__ float* et_ptr(int t){ return (t==0)?g_et0:((t==1)?g_et1:g_et2); }
__device__ __forceinline__ void split2(float v, __half& a, __half& b){
    a = __float2half_rn(v);
    float r = v - __half2float(a);
    b = __float2half_rn(r * RSCALE);
}
__device__ __forceinline__ float fsig(float x){ return __fdividef(1.f, 1.f + __expf(-x)); }
__device__ __forceinline__ float ftanh(float x){ return 1.f - __fdividef(2.f, 1.f + __expf(2.f*x)); }

// ================= baseline-PTX tensor helpers =================
__device__ __forceinline__ uint32_t smem_u32(const void* p){
    uint32_t a;
    asm("{ .reg .u64 t; cvta.to.shared.u64 t, %1; cvt.u32.u64 %0, t; }" : "=r"(a) : "l"(p));
    return a;
}
__device__ __forceinline__ void ldsm4(uint32_t* r, uint32_t addr){
    asm volatile("ldmatrix.sync.aligned.m8n8.x4.shared.b16 {%0,%1,%2,%3}, [%4];"
        : "=r"(r[0]), "=r"(r[1]), "=r"(r[2]), "=r"(r[3]) : "r"(addr));
}
__device__ __forceinline__ void mma16816(float* c, const uint32_t* a, const uint32_t* b){
    asm volatile("mma.sync.aligned.m16n8k16.row.col.f32.f16.f16.f32 "
        "{%0,%1,%2,%3}, {%4,%5,%6,%7}, {%8,%9}, {%0,%1,%2,%3};"
        : "+f"(c[0]), "+f"(c[1]), "+f"(c[2]), "+f"(c[3])
        : "r"(a[0]), "r"(a[1]), "r"(a[2]), "r"(a[3]), "r"(b[0]), "r"(b[1]));
}
__device__ __forceinline__ void cpa16(uint32_t d, const void* s){
    asm volatile("cp.async.cg.shared.global [%0], [%1], 16;" :: "r"(d), "l"(s));
}
#define CP_COMMIT() asm volatile("cp.async.commit_group;" ::: "memory")
#define CP_WAIT0()  asm volatile("cp.async.wait_group 0;" ::: "memory")
#define CP_WAIT1()  asm volatile("cp.async.wait_group 1;" ::: "memory")

// ================= prep kernels =================
__global__ void pack_b_kernel(const float* __restrict__ Whh, const float* __restrict__ W2,
                              const float* __restrict__ Wih, const float* __restrict__ W1,
                              const float* __restrict__ bih, const float* __restrict__ bhh){
    int row = blockIdx.x, k = threadIdx.x, j = row*256 + k;
    float ws = (row < 1024) ? Whh[j] : W2[(size_t)(row-1024)*256 + k];
    float wp = (row < 1024) ? Wih[j] : W1[(size_t)(row-1024)*256 + k];
    split2(ws, g_bs0[j], g_bs1[j]);
    split2(wp, g_bp0[j], g_bp1[j]);
    if (row < 4) g_bias[j] = bih[j] + bhh[j];
}

__global__ void split_enc_kernel(const float* __restrict__ e0, const float* __restrict__ e1,
                                 const float* __restrict__ e2){
    int k = threadIdx.x;
#pragma unroll
    for (int rr = 0; rr < 8; rr++){
        size_t R = (size_t)blockIdx.x*8 + rr;          // 0..479999
        int t = (int)(R / ERT);
        const float* e = (t==0)?e0:((t==1)?e1:e2);
        float v = e[(R - (size_t)t*ERT)*256 + k];
        split2(v, g_es0[R*256+k], g_es1[R*256+k]);
    }
}

__global__ void h0_kernel(const float* __restrict__ e0, const float* __restrict__ e1,
                          const float* __restrict__ e2){
    int r = blockIdx.x, k = threadIdx.x;
    int t = r / NPT, n = r % NPT;
    const float* e = ((t==0)?e0:((t==1)?e1:e2)) + (size_t)n*(Ssz*256) + k;
    float s = 0.f;
#pragma unroll 1
    for (int ss = 0; ss < Ssz; ss++) s += e[ss*256];
    g_c[r*256+k] = s;
    split2(s, g_h0s[r*256+k], g_h1s[r*256+k]);
}

// ================= emulated-fp32 GEMM via mma.sync fp16 (2-way split, 3 products) =================
// CTA tile 128x64, warp tile 32x32 (4x2 warps), 2 CTAs/SM.
// grid.x = n-block (fast -> co-resident CTAs share the A tile in L2), grid.y = m-block.
// Output split: n < 1024 -> Cg (width 1024), n >= 1024 -> Cd (width 256).
#define ASTR   72
#define ATILE  (128*ASTR*2)           // 18432 B
#define BTILE  (64*ASTR*2)            // 9216 B
#define STAGE  (2*ATILE + 2*BTILE)    // 55296 B : A0 A1 B0 B1
#define GSMEM  (2*STAGE)              // 110592 B

__global__ __launch_bounds__(256, 2) void gemm_kernel(
    const __half* __restrict__ A0, const __half* __restrict__ A1,
    const __half* __restrict__ B0, const __half* __restrict__ B1,
    float* __restrict__ Cg, float* __restrict__ Cd)
{
    extern __shared__ __half sh[];
    uint32_t sb = smem_u32(sh);

    const int tid = threadIdx.x, lane = tid & 31, w = tid >> 5;
    const int wm = w & 3, wn = w >> 2;
    const size_t m0 = (size_t)blockIdx.y * 128;
    const int n0 = blockIdx.x * 64;

    float acc0[2][4][4], acc1[2][4][4];
#pragma unroll
    for (int i = 0; i < 2; i++)
#pragma unroll
        for (int j = 0; j < 4; j++)
#pragma unroll
            for (int q = 0; q < 4; q++){ acc0[i][j][q] = 0.f; acc1[i][j][q] = 0.f; }

    const __half* Asrc[2] = { A0 + m0*256, A1 + m0*256 };
    const __half* Bsrc[2] = { B0 + (size_t)n0*256, B1 + (size_t)n0*256 };

    const int arow = wm*32 + (lane & 15);
    const int akof = (lane >> 4) * 8;
    const int brow = wn*32 + (lane & 7) + ((lane >> 4) << 3);
    const int bkof = ((lane >> 3) & 1) * 8;

    auto load_stage = [&](int c){
        uint32_t base = sb + (uint32_t)(c & 1)*STAGE;
#pragma unroll
        for (int t = 0; t < 2; t++){
            const __half* src = Asrc[t] + c*64;
#pragma unroll
            for (int i = 0; i < 4; i++){
                int id = tid + i*256, row = id >> 3, seg = id & 7;
                cpa16(base + t*ATILE + (uint32_t)(row*ASTR + seg*8)*2,
                      src + (size_t)row*256 + seg*8);
            }
        }
#pragma unroll
        for (int t = 0; t < 2; t++){
            const __half* src = Bsrc[t] + c*64;
#pragma unroll
            for (int i = 0; i < 2; i++){
                int id = tid + i*256, row = id >> 3, seg = id & 7;
                cpa16(base + 2*ATILE + t*BTILE + (uint32_t)(row*ASTR + seg*8)*2,
                      src + (size_t)row*256 + seg*8);
            }
        }
        CP_COMMIT();
    };

    load_stage(0);
#pragma unroll 1
    for (int c = 0; c < 4; c++){
        if (c + 1 < 4){ load_stage(c + 1); CP_WAIT1(); }
        else CP_WAIT0();
        __syncthreads();
        uint32_t base = sb + (uint32_t)(c & 1)*STAGE;
        uint32_t a0b = base, a1b = base + ATILE;
        uint32_t b0b = base + 2*ATILE, b1b = b0b + BTILE;
#pragma unroll
        for (int ks = 0; ks < 4; ks++){
            uint32_t b0f[4][2], b1f[4][2];
#pragma unroll
            for (int f2 = 0; f2 < 2; f2++){
                uint32_t off = (uint32_t)((brow + f2*16)*ASTR + ks*16 + bkof)*2;
                uint32_t r[4];
                ldsm4(r, b0b + off);
                b0f[f2*2][0] = r[0]; b0f[f2*2][1] = r[1];
                b0f[f2*2+1][0] = r[2]; b0f[f2*2+1][1] = r[3];
                ldsm4(r, b1b + off);
                b1f[f2*2][0] = r[0]; b1f[f2*2][1] = r[1];
                b1f[f2*2+1][0] = r[2]; b1f[f2*2+1][1] = r[3];
            }
#pragma unroll
            for (int fm = 0; fm < 2; fm++){
                uint32_t aoff = (uint32_t)((arow + fm*16)*ASTR + ks*16 + akof)*2;
                uint32_t a0f[4], a1f[4];
                ldsm4(a0f, a0b + aoff);
                ldsm4(a1f, a1b + aoff);
#pragma unroll
                for (int fn = 0; fn < 4; fn++){
                    mma16816(acc0[fm][fn], a0f, b0f[fn]);
                    mma16816(acc1[fm][fn], a0f, b1f[fn]);
                    mma16816(acc1[fm][fn], a1f, b0f[fn]);
                }
            }
        }
        __syncthreads();
    }

    // epilogue: route n<1024 -> Cg (w=1024), n>=1024 -> Cd (w=256)
    const bool isg = (n0 < 1024);
    float* Cb = isg ? Cg : Cd;
    const int cw = isg ? 1024 : 256;
    const int col = (isg ? n0 : (n0 - 1024)) + wn*32 + 2*(lane & 3);
#pragma unroll
    for (int fm = 0; fm < 2; fm++){
        size_t mrow = m0 + wm*32 + fm*16 + (lane >> 2);
        float* cp0 = Cb + mrow*cw     + col;
        float* cp1 = Cb + (mrow+8)*cw + col;
#pragma unroll
        for (int fn = 0; fn < 4; fn++){
            *(float2*)(cp0 + fn*8) = make_float2(fmaf(acc1[fm][fn][0], RINV, acc0[fm][fn][0]),
                                                 fmaf(acc1[fm][fn][1], RINV, acc0[fm][fn][1]));
            *(float2*)(cp1 + fn*8) = make_float2(fmaf(acc1[fm][fn][2], RINV, acc0[fm][fn][2]),
                                                 fmaf(acc1[fm][fn][3], RINV, acc0[fm][fn][3]));
        }
    }
}

// ================= cell0: initial cell (x=0, no gather) =================
__global__ __launch_bounds__(256) void cell0_kernel(){
    int k = threadIdx.x;
#pragma unroll
    for (int rr = 0; rr < 4; rr++){
        int r = blockIdx.x*4 + rr;
        const float* g = g_graw + (size_t)r*1024;
        float i = fsig (g[k]     + g_bias[k]);
        float f = fsig (g[256+k] + g_bias[256+k]);
        float gv= ftanh(g[512+k] + g_bias[512+k]);
        float o = fsig (g[768+k] + g_bias[768+k]);
        float cn = fmaf(f, g_c[r*256+k], i*gv);
        g_c[r*256+k] = cn;
        split2(o * ftanh(cn), g_h0s[r*256+k], g_h1s[r*256+k]);
    }
}

// ================= fused attention(step) + cell(step+1) =================
__global__ __launch_bounds__(256) void attn_cell_kernel(int step, int do_cell,
                                                        const float* __restrict__ vt,
                                                        float* __restrict__ out){
    __shared__ float dec_s[256], vt_s[256], u_s[Ssz];
    __shared__ int idx_sh;
    int tid = threadIdx.x, wid = tid >> 5, lane = tid & 31;
    int r = blockIdx.x;                       // global row 0..9599
    int t = r / NPT, n = r % NPT;
    dec_s[tid] = g_dec[(size_t)r*256 + tid];
    vt_s[tid]  = vt[tid];
    __syncthreads();

    const float* eb = et_ptr(t) + (size_t)n*Ssz*256;   // fully contiguous 51.2 KB
#pragma unroll 1
    for (int s = wid; s < Ssz; s += 8){
        const float4* ep = (const float4*)(eb + (size_t)s*256);
        float4 e0 = ep[lane], e1 = ep[32 + lane];
        float4 d0 = *(const float4*)(&dec_s[4*lane]);
        float4 d1 = *(const float4*)(&dec_s[128 + 4*lane]);
        float4 v0 = *(const float4*)(&vt_s[4*lane]);
        float4 v1 = *(const float4*)(&vt_s[128 + 4*lane]);
        float p0 = ftanh(e0.x + d0.x) * v0.x;
        float p1 = ftanh(e0.y + d0.y) * v0.y;
        p0 = fmaf(ftanh(e0.z + d0.z), v0.z, p0);
        p1 = fmaf(ftanh(e0.w + d0.w), v0.w, p1);
        p0 = fmaf(ftanh(e1.x + d1.x), v1.x, p0);
        p1 = fmaf(ftanh(e1.y + d1.y), v1.y, p1);
        p0 = fmaf(ftanh(e1.z + d1.z), v1.z, p0);
        p1 = fmaf(ftanh(e1.w + d1.w), v1.w, p1);
        float p = p0 + p1;
#pragma unroll
        for (int off = 16; off; off >>= 1) p += __shfl_xor_sync(0xffffffffu, p, off);
        if (lane == 0) u_s[s] = p;
    }
    __syncthreads();

    if (wid == 0){
        float ua = u_s[lane];
        float ub = (lane + 32 < Ssz) ? u_s[lane + 32] : -CUDART_INF_F;
        float bm = ua; int bi = lane;
        if (ub > bm){ bm = ub; bi = lane + 32; }
#pragma unroll
        for (int off = 16; off; off >>= 1){
            float vm = __shfl_xor_sync(0xffffffffu, bm, off);
            int   vi = __shfl_xor_sync(0xffffffffu, bi, off);
            if (vm > bm || (vm == bm && vi < bi)){ bm = vm; bi = vi; }
        }
        float ea = __expf(ua - bm);
        float eb2 = (lane + 32 < Ssz) ? __expf(ub - bm) : 0.f;
        float sm = ea + eb2;
#pragma unroll
        for (int off = 16; off; off >>= 1) sm += __shfl_xor_sync(0xffffffffu, sm, off);
        float inv = 1.0f / sm;
        float* so = out + (size_t)t*8160000 + (size_t)n*2500 + step*50;
        so[lane] = ea * inv;
        if (lane + 32 < Ssz) so[lane + 32] = eb2 * inv;
        if (lane == 0){
            idx_sh = bi;
            out[(size_t)t*8160000 + 8000000 + (size_t)n*50 + step] = (float)bi;
        }
    }
    __syncthreads();

    if (do_cell){
        int k = tid;
        const float* g = g_graw + (size_t)r*1024;
        const float* ex = gx_ptr(t) + (size_t)(n*Ssz + idx_sh)*1024;
        float i = fsig (g[k]     + ex[k]     + g_bias[k]);
        float f = fsig (g[256+k] + ex[256+k] + g_bias[256+k]);
        float gv= ftanh(g[512+k] + ex[512+k] + g_bias[512+k]);
        float o = fsig (g[768+k] + ex[768+k] + g_bias[768+k]);
        float cn = fmaf(f, g_c[r*256+k], i*gv);
        g_c[r*256+k] = cn;
        split2(o * ftanh(cn), g_h0s[r*256+k], g_h1s[r*256+k]);
    }
}

// ================= launch =================
extern "C" void kernel_launch(void* const* d_in, const int* in_sizes, int n_in,
                              void* d_out, int out_size){
    const float* home = (const float*)d_in[0];
    const float* vis  = (const float*)d_in[1];
    const float* team = (const float*)d_in[2];
    const float* Wih  = (const float*)d_in[3];
    const float* Whh  = (const float*)d_in[4];
    const float* bih  = (const float*)d_in[5];
    const float* bhh  = (const float*)d_in[6];
    const float* W1   = (const float*)d_in[7];
    const float* W2   = (const float*)d_in[8];
    const float* vt   = (const float*)d_in[9];
    float* out = (float*)d_out;

    cudaFuncSetAttribute(gemm_kernel, cudaFuncAttributeMaxDynamicSharedMemorySize, GSMEM);

    pack_b_kernel<<<NB, 256>>>(Whh, W2, Wih, W1, bih, bhh);
    split_enc_kernel<<<60000, 256>>>(home, vis, team);
    h0_kernel<<<NROW, 256>>>(home, vis, team);

    __half *es0, *es1, *bp0, *bp1, *bs0, *bs1, *h0, *h1;
    float *gx0, *gx1, *gx2, *et0, *et1, *et2, *graw, *dec;
    cudaGetSymbolAddress((void**)&es0, g_es0);  cudaGetSymbolAddress((void**)&es1, g_es1);
    cudaGetSymbolAddress((void**)&bp0, g_bp0);  cudaGetSymbolAddress((void**)&bp1, g_bp1);
    cudaGetSymbolAddress((void**)&bs0, g_bs0);  cudaGetSymbolAddress((void**)&bs1, g_bs1);
    cudaGetSymbolAddress((void**)&h0,  g_h0s);  cudaGetSymbolAddress((void**)&h1,  g_h1s);
    cudaGetSymbolAddress((void**)&gx0, g_gx0);  cudaGetSymbolAddress((void**)&gx1, g_gx1);
    cudaGetSymbolAddress((void**)&gx2, g_gx2);
    cudaGetSymbolAddress((void**)&et0, g_et0);  cudaGetSymbolAddress((void**)&et1, g_et1);
    cudaGetSymbolAddress((void**)&et2, g_et2);
    cudaGetSymbolAddress((void**)&graw, g_graw); cudaGetSymbolAddress((void**)&dec, g_dec);

    float* gxs[3] = {gx0, gx1, gx2};
    float* ets[3] = {et0, et1, et2};
    for (int t = 0; t < 3; t++){
        size_t off = (size_t)t * ERT * 256;
        gemm_kernel<<<dim3(20, 1250), 256, GSMEM>>>(es0 + off, es1 + off, bp0, bp1,
                                                    gxs[t], ets[t]);
    }

    // bootstrap: gates from h0 -> cell0 -> gates+dec
    gemm_kernel<<<dim3(20, 75), 256, GSMEM>>>(h0, h1, bs0, bs1, graw, dec);
    cell0_kernel<<<NROW/4, 256>>>();
    gemm_kernel<<<dim3(20, 75), 256, GSMEM>>>(h0, h1, bs0, bs1, graw, dec);

    for (int i = 0; i < Ssz; i++){
        attn_cell_kernel<<<NROW, 256>>>(i, (i + 1 < Ssz) ? 1 : 0, vt, out);
        if (i + 1 < Ssz)
            gemm_kernel<<<dim3(20, 75), 256, GSMEM>>>(h0, h1, bs0, bs1, graw, dec);
    }
}

// round 9
// speedup vs baseline: 2.1036x; 1.0019x over previous
#include <cuda_runtime.h>
#include <cuda_fp16.h>
#include <math_constants.h>
#include <cstdint>

#define Ssz  50
#define NPT  3200
#define NROW 9600
#define ERT  160000
#define NB   1280

#define RSCALE   2048.0f          // residual scale 2^11
#define RINV     (1.0f/2048.0f)

#define H1ROWS 4864               // 38 * 128
#define H2ROWS 4736               // 37 * 128

// ================= static device scratch (no allocation) =================
static __device__ __half g_es0[(size_t)480000*256], g_es1[(size_t)480000*256];
static __device__ float g_gx0[(size_t)ERT*1024], g_gx1[(size_t)ERT*1024], g_gx2[(size_t)ERT*1024];
static __device__ float g_et0[(size_t)ERT*256],  g_et1[(size_t)ERT*256],  g_et2[(size_t)ERT*256];
static __device__ __half g_h0s[NROW*256], g_h1s[NROW*256];
static __device__ float g_c[NROW*256];
static __device__ float g_graw[(size_t)NROW*1024];
static __device__ float g_dec[(size_t)NROW*256];
static __device__ __half g_bs0[NB*256], g_bs1[NB*256];   // [Whh;W2] splits
static __device__ __half g_bp0[NB*256], g_bp1[NB*256];   // [Wih;W1] splits
static __device__ float g_bias[1024];

__device__ __forceinline__ float* gx_ptr(int t){ return (t==0)?g_gx0:((t==1)?g_gx1:g_gx2); }
__device__ __forceinline__ float* et_ptr(int t){ return (t==0)?g_et0:((t==1)?g_et1:g_et2); }
__device__ __forceinline__ void split2(float v, __half& a, __half& b){
    a = __float2half_rn(v);
    float r = v - __half2float(a);
    b = __float2half_rn(r * RSCALE);
}
__device__ __forceinline__ float fsig(float x){ return __fdividef(1.f, 1.f + __expf(-x)); }
__device__ __forceinline__ float ftanh(float x){ return 1.f - __fdividef(2.f, 1.f + __expf(2.f*x)); }

// ================= baseline-PTX tensor helpers =================
__device__ __forceinline__ uint32_t smem_u32(const void* p){
    uint32_t a;
    asm("{ .reg .u64 t; cvta.to.shared.u64 t, %1; cvt.u32.u64 %0, t; }" : "=r"(a) : "l"(p));
    return a;
}
__device__ __forceinline__ void ldsm4(uint32_t* r, uint32_t addr){
    asm volatile("ldmatrix.sync.aligned.m8n8.x4.shared.b16 {%0,%1,%2,%3}, [%4];"
        : "=r"(r[0]), "=r"(r[1]), "=r"(r[2]), "=r"(r[3]) : "r"(addr));
}
__device__ __forceinline__ void mma16816(float* c, const uint32_t* a, const uint32_t* b){
    asm volatile("mma.sync.aligned.m16n8k16.row.col.f32.f16.f16.f32 "
        "{%0,%1,%2,%3}, {%4,%5,%6,%7}, {%8,%9}, {%0,%1,%2,%3};"
        : "+f"(c[0]), "+f"(c[1]), "+f"(c[2]), "+f"(c[3])
        : "r"(a[0]), "r"(a[1]), "r"(a[2]), "r"(a[3]), "r"(b[0]), "r"(b[1]));
}
__device__ __forceinline__ void cpa16(uint32_t d, const void* s){
    asm volatile("cp.async.cg.shared.global [%0], [%1], 16;" :: "r"(d), "l"(s));
}
#define CP_COMMIT() asm volatile("cp.async.commit_group;" ::: "memory")
#define CP_WAIT0()  asm volatile("cp.async.wait_group 0;" ::: "memory")
#define CP_WAIT1()  asm volatile("cp.async.wait_group 1;" ::: "memory")

// ================= prep kernels =================
__global__ void pack_b_kernel(const float* __restrict__ Whh, const float* __restrict__ W2,
                              const float* __restrict__ Wih, const float* __restrict__ W1,
                              const float* __restrict__ bih, const float* __restrict__ bhh){
    int row = blockIdx.x, k = threadIdx.x, j = row*256 + k;
    float ws = (row < 1024) ? Whh[j] : W2[(size_t)(row-1024)*256 + k];
    float wp = (row < 1024) ? Wih[j] : W1[(size_t)(row-1024)*256 + k];
    split2(ws, g_bs0[j], g_bs1[j]);
    split2(wp, g_bp0[j], g_bp1[j]);
    if (row < 4) g_bias[j] = bih[j] + bhh[j];
}

__global__ void split_enc_kernel(const float* __restrict__ e0, const float* __restrict__ e1,
                                 const float* __restrict__ e2){
    int k = threadIdx.x;
#pragma unroll
    for (int rr = 0; rr < 8; rr++){
        size_t R = (size_t)blockIdx.x*8 + rr;          // 0..479999
        int t = (int)(R / ERT);
        const float* e = (t==0)?e0:((t==1)?e1:e2);
        float v = e[(R - (size_t)t*ERT)*256 + k];
        split2(v, g_es0[R*256+k], g_es1[R*256+k]);
    }
}

__global__ void h0_kernel(const float* __restrict__ e0, const float* __restrict__ e1,
                          const float* __restrict__ e2){
    int r = blockIdx.x, k = threadIdx.x;
    int t = r / NPT, n = r % NPT;
    const float* e = ((t==0)?e0:((t==1)?e1:e2)) + (size_t)n*(Ssz*256) + k;
    float s = 0.f;
#pragma unroll 1
    for (int ss = 0; ss < Ssz; ss++) s += e[ss*256];
    g_c[r*256+k] = s;
    split2(s, g_h0s[r*256+k], g_h1s[r*256+k]);
}

// ================= emulated-fp32 GEMM via mma.sync fp16 (2-way split, 3 products) =================
// CTA tile 128x64, warp tile 32x32 (4x2 warps), 2 CTAs/SM.
// grid.x = n-block (fast -> co-resident CTAs share the A tile in L2), grid.y = m-block.
// Output split: n < 1024 -> Cg (width 1024), n >= 1024 -> Cd (width 256).
#define ASTR   72
#define ATILE  (128*ASTR*2)           // 18432 B
#define BTILE  (64*ASTR*2)            // 9216 B
#define STAGE  (2*ATILE + 2*BTILE)    // 55296 B : A0 A1 B0 B1
#define GSMEM  (2*STAGE)              // 110592 B

__global__ __launch_bounds__(256, 2) void gemm_kernel(
    const __half* __restrict__ A0, const __half* __restrict__ A1,
    const __half* __restrict__ B0, const __half* __restrict__ B1,
    float* __restrict__ Cg, float* __restrict__ Cd)
{
    extern __shared__ __half sh[];
    uint32_t sb = smem_u32(sh);

    const int tid = threadIdx.x, lane = tid & 31, w = tid >> 5;
    const int wm = w & 3, wn = w >> 2;
    const size_t m0 = (size_t)blockIdx.y * 128;
    const int n0 = blockIdx.x * 64;

    float acc0[2][4][4], acc1[2][4][4];
#pragma unroll
    for (int i = 0; i < 2; i++)
#pragma unroll
        for (int j = 0; j < 4; j++)
#pragma unroll
            for (int q = 0; q < 4; q++){ acc0[i][j][q] = 0.f; acc1[i][j][q] = 0.f; }

    const __half* Asrc[2] = { A0 + m0*256, A1 + m0*256 };
    const __half* Bsrc[2] = { B0 + (size_t)n0*256, B1 + (size_t)n0*256 };

    const int arow = wm*32 + (lane & 15);
    const int akof = (lane >> 4) * 8;
    const int brow = wn*32 + (lane & 7) + ((lane >> 4) << 3);
    const int bkof = ((lane >> 3) & 1) * 8;

    auto load_stage = [&](int c){
        uint32_t base = sb + (uint32_t)(c & 1)*STAGE;
#pragma unroll
        for (int t = 0; t < 2; t++){
            const __half* src = Asrc[t] + c*64;
#pragma unroll
            for (int i = 0; i < 4; i++){
                int id = tid + i*256, row = id >> 3, seg = id & 7;
                cpa16(base + t*ATILE + (uint32_t)(row*ASTR + seg*8)*2,
                      src + (size_t)row*256 + seg*8);
            }
        }
#pragma unroll
        for (int t = 0; t < 2; t++){
            const __half* src = Bsrc[t] + c*64;
#pragma unroll
            for (int i = 0; i < 2; i++){
                int id = tid + i*256, row = id >> 3, seg = id & 7;
                cpa16(base + 2*ATILE + t*BTILE + (uint32_t)(row*ASTR + seg*8)*2,
                      src + (size_t)row*256 + seg*8);
            }
        }
        CP_COMMIT();
    };

    load_stage(0);
#pragma unroll 1
    for (int c = 0; c < 4; c++){
        if (c + 1 < 4){ load_stage(c + 1); CP_WAIT1(); }
        else CP_WAIT0();
        __syncthreads();
        uint32_t base = sb + (uint32_t)(c & 1)*STAGE;
        uint32_t a0b = base, a1b = base + ATILE;
        uint32_t b0b = base + 2*ATILE, b1b = b0b + BTILE;
#pragma unroll
        for (int ks = 0; ks < 4; ks++){
            uint32_t b0f[4][2], b1f[4][2];
#pragma unroll
            for (int f2 = 0; f2 < 2; f2++){
                uint32_t off = (uint32_t)((brow + f2*16)*ASTR + ks*16 + bkof)*2;
                uint32_t r[4];
                ldsm4(r, b0b + off);
                b0f[f2*2][0] = r[0]; b0f[f2*2][1] = r[1];
                b0f[f2*2+1][0] = r[2]; b0f[f2*2+1][1] = r[3];
                ldsm4(r, b1b + off);
                b1f[f2*2][0] = r[0]; b1f[f2*2][1] = r[1];
                b1f[f2*2+1][0] = r[2]; b1f[f2*2+1][1] = r[3];
            }
#pragma unroll
            for (int fm = 0; fm < 2; fm++){
                uint32_t aoff = (uint32_t)((arow + fm*16)*ASTR + ks*16 + akof)*2;
                uint32_t a0f[4], a1f[4];
                ldsm4(a0f, a0b + aoff);
                ldsm4(a1f, a1b + aoff);
#pragma unroll
                for (int fn = 0; fn < 4; fn++){
                    mma16816(acc0[fm][fn], a0f, b0f[fn]);
                    mma16816(acc1[fm][fn], a0f, b1f[fn]);
                    mma16816(acc1[fm][fn], a1f, b0f[fn]);
                }
            }
        }
        __syncthreads();
    }

    // epilogue: route n<1024 -> Cg (w=1024), n>=1024 -> Cd (w=256)
    const bool isg = (n0 < 1024);
    float* Cb = isg ? Cg : Cd;
    const int cw = isg ? 1024 : 256;
    const int col = (isg ? n0 : (n0 - 1024)) + wn*32 + 2*(lane & 3);
#pragma unroll
    for (int fm = 0; fm < 2; fm++){
        size_t mrow = m0 + wm*32 + fm*16 + (lane >> 2);
        float* cp0 = Cb + mrow*cw     + col;
        float* cp1 = Cb + (mrow+8)*cw + col;
#pragma unroll
        for (int fn = 0; fn < 4; fn++){
            *(float2*)(cp0 + fn*8) = make_float2(fmaf(acc1[fm][fn][0], RINV, acc0[fm][fn][0]),
                                                 fmaf(acc1[fm][fn][1], RINV, acc0[fm][fn][1]));
            *(float2*)(cp1 + fn*8) = make_float2(fmaf(acc1[fm][fn][2], RINV, acc0[fm][fn][2]),
                                                 fmaf(acc1[fm][fn][3], RINV, acc0[fm][fn][3]));
        }
    }
}

// ================= cell0: initial cell (x=0, no gather) =================
__global__ __launch_bounds__(256) void cell0_kernel(int r0){
    int k = threadIdx.x;
#pragma unroll
    for (int rr = 0; rr < 4; rr++){
        int r = r0 + blockIdx.x*4 + rr;
        const float* g = g_graw + (size_t)r*1024;
        float i = fsig (g[k]     + g_bias[k]);
        float f = fsig (g[256+k] + g_bias[256+k]);
        float gv= ftanh(g[512+k] + g_bias[512+k]);
        float o = fsig (g[768+k] + g_bias[768+k]);
        float cn = fmaf(f, g_c[r*256+k], i*gv);
        g_c[r*256+k] = cn;
        split2(o * ftanh(cn), g_h0s[r*256+k], g_h1s[r*256+k]);
    }
}

// ================= fused attention(step) + cell(step+1) =================
__global__ __launch_bounds__(256) void attn_cell_kernel(int step, int do_cell, int r0,
                                                        const float* __restrict__ vt,
                                                        float* __restrict__ out){
    __shared__ float dec_s[256], vt_s[256], u_s[Ssz];
    __shared__ int idx_sh;
    int tid = threadIdx.x, wid = tid >> 5, lane = tid & 31;
    int r = r0 + blockIdx.x;                  // global row 0..9599
    int t = r / NPT, n = r % NPT;
    dec_s[tid] = g_dec[(size_t)r*256 + tid];
    vt_s[tid]  = vt[tid];
    __syncthreads();

    const float* eb = et_ptr(t) + (size_t)n*Ssz*256;   // fully contiguous 51.2 KB
#pragma unroll 1
    for (int s = wid; s < Ssz; s += 8){
        const float4* ep = (const float4*)(eb + (size_t)s*256);
        float4 e0 = ep[lane], e1 = ep[32 + lane];
        float4 d0 = *(const float4*)(&dec_s[4*lane]);
        float4 d1 = *(const float4*)(&dec_s[128 + 4*lane]);
        float4 v0 = *(const float4*)(&vt_s[4*lane]);
        float4 v1 = *(const float4*)(&vt_s[128 + 4*lane]);
        float p0 = ftanh(e0.x + d0.x) * v0.x;
        float p1 = ftanh(e0.y + d0.y) * v0.y;
        p0 = fmaf(ftanh(e0.z + d0.z), v0.z, p0);
        p1 = fmaf(ftanh(e0.w + d0.w), v0.w, p1);
        p0 = fmaf(ftanh(e1.x + d1.x), v1.x, p0);
        p1 = fmaf(ftanh(e1.y + d1.y), v1.y, p1);
        p0 = fmaf(ftanh(e1.z + d1.z), v1.z, p0);
        p1 = fmaf(ftanh(e1.w + d1.w), v1.w, p1);
        float p = p0 + p1;
#pragma unroll
        for (int off = 16; off; off >>= 1) p += __shfl_xor_sync(0xffffffffu, p, off);
        if (lane == 0) u_s[s] = p;
    }
    __syncthreads();

    if (wid == 0){
        float ua = u_s[lane];
        float ub = (lane + 32 < Ssz) ? u_s[lane + 32] : -CUDART_INF_F;
        float bm = ua; int bi = lane;
        if (ub > bm){ bm = ub; bi = lane + 32; }
#pragma unroll
        for (int off = 16; off; off >>= 1){
            float vm = __shfl_xor_sync(0xffffffffu, bm, off);
            int   vi = __shfl_xor_sync(0xffffffffu, bi, off);
            if (vm > bm || (vm == bm && vi < bi)){ bm = vm; bi = vi; }
        }
        float ea = __expf(ua - bm);
        float eb2 = (lane + 32 < Ssz) ? __expf(ub - bm) : 0.f;
        float sm = ea + eb2;
#pragma unroll
        for (int off = 16; off; off >>= 1) sm += __shfl_xor_sync(0xffffffffu, sm, off);
        float inv = 1.0f / sm;
        float* so = out + (size_t)t*8160000 + (size_t)n*2500 + step*50;
        so[lane] = ea * inv;
        if (lane + 32 < Ssz) so[lane + 32] = eb2 * inv;
        if (lane == 0){
            idx_sh = bi;
            out[(size_t)t*8160000 + 8000000 + (size_t)n*50 + step] = (float)bi;
        }
    }
    __syncthreads();

    if (do_cell){
        int k = tid;
        const float* g = g_graw + (size_t)r*1024;
        const float* ex = gx_ptr(t) + (size_t)(n*Ssz + idx_sh)*1024;
        float i = fsig (g[k]     + ex[k]     + g_bias[k]);
        float f = fsig (g[256+k] + ex[256+k] + g_bias[256+k]);
        float gv= ftanh(g[512+k] + ex[512+k] + g_bias[512+k]);
        float o = fsig (g[768+k] + ex[768+k] + g_bias[768+k]);
        float cn = fmaf(f, g_c[r*256+k], i*gv);
        g_c[r*256+k] = cn;
        split2(o * ftanh(cn), g_h0s[r*256+k], g_h1s[r*256+k]);
    }
}

// ================= launch =================
extern "C" void kernel_launch(void* const* d_in, const int* in_sizes, int n_in,
                              void* d_out, int out_size){
    const float* home = (const float*)d_in[0];
    const float* vis  = (const float*)d_in[1];
    const float* team = (const float*)d_in[2];
    const float* Wih  = (const float*)d_in[3];
    const float* Whh  = (const float*)d_in[4];
    const float* bih  = (const float*)d_in[5];
    const float* bhh  = (const float*)d_in[6];
    const float* W1   = (const float*)d_in[7];
    const float* W2   = (const float*)d_in[8];
    const float* vt   = (const float*)d_in[9];
    float* out = (float*)d_out;

    cudaFuncSetAttribute(gemm_kernel, cudaFuncAttributeMaxDynamicSharedMemorySize, GSMEM);

    pack_b_kernel<<<NB, 256>>>(Whh, W2, Wih, W1, bih, bhh);
    split_enc_kernel<<<60000, 256>>>(home, vis, team);
    h0_kernel<<<NROW, 256>>>(home, vis, team);

    __half *es0, *es1, *bp0, *bp1, *bs0, *bs1, *h0, *h1;
    float *gx0, *gx1, *gx2, *et0, *et1, *et2, *graw, *dec;
    cudaGetSymbolAddress((void**)&es0, g_es0);  cudaGetSymbolAddress((void**)&es1, g_es1);
    cudaGetSymbolAddress((void**)&bp0, g_bp0);  cudaGetSymbolAddress((void**)&bp1, g_bp1);
    cudaGetSymbolAddress((void**)&bs0, g_bs0);  cudaGetSymbolAddress((void**)&bs1, g_bs1);
    cudaGetSymbolAddress((void**)&h0,  g_h0s);  cudaGetSymbolAddress((void**)&h1,  g_h1s);
    cudaGetSymbolAddress((void**)&gx0, g_gx0);  cudaGetSymbolAddress((void**)&gx1, g_gx1);
    cudaGetSymbolAddress((void**)&gx2, g_gx2);
    cudaGetSymbolAddress((void**)&et0, g_et0);  cudaGetSymbolAddress((void**)&et1, g_et1);
    cudaGetSymbolAddress((void**)&et2, g_et2);
    cudaGetSymbolAddress((void**)&graw, g_graw); cudaGetSymbolAddress((void**)&dec, g_dec);

    float* gxs[3] = {gx0, gx1, gx2};
    float* ets[3] = {et0, et1, et2};
    for (int t = 0; t < 3; t++){
        size_t off = (size_t)t * ERT * 256;
        gemm_kernel<<<dim3(20, 1250), 256, GSMEM>>>(es0 + off, es1 + off, bp0, bp1,
                                                    gxs[t], ets[t]);
    }

    // ---- fork a second stream: half A (rows 0..4863) on stream 0, half B on s1 ----
    cudaStream_t s1;
    cudaStreamCreateWithFlags(&s1, cudaStreamNonBlocking);
    cudaEvent_t evFork, evJoin;
    cudaEventCreateWithFlags(&evFork, cudaEventDisableTiming);
    cudaEventCreateWithFlags(&evJoin, cudaEventDisableTiming);

    cudaEventRecord(evFork, 0);
    cudaStreamWaitEvent(s1, evFork, 0);

    const int r0s[2]   = {0, H1ROWS};
    const int rows[2]  = {H1ROWS, H2ROWS};
    cudaStream_t strm[2] = {0, s1};

    for (int hlf = 0; hlf < 2; hlf++){
        cudaStream_t st = strm[hlf];
        int r0 = r0s[hlf], nr = rows[hlf];
        const __half* A0 = h0 + (size_t)r0*256;
        const __half* A1 = h1 + (size_t)r0*256;
        float* Cg = graw + (size_t)r0*1024;
        float* Cd = dec  + (size_t)r0*256;
        dim3 ggrid(20, nr/128);

        gemm_kernel<<<ggrid, 256, GSMEM, st>>>(A0, A1, bs0, bs1, Cg, Cd);
        cell0_kernel<<<nr/4, 256, 0, st>>>(r0);
        gemm_kernel<<<ggrid, 256, GSMEM, st>>>(A0, A1, bs0, bs1, Cg, Cd);
        for (int i = 0; i < Ssz; i++){
            attn_cell_kernel<<<nr, 256, 0, st>>>(i, (i + 1 < Ssz) ? 1 : 0, r0, vt, out);
            if (i + 1 < Ssz)
                gemm_kernel<<<ggrid, 256, GSMEM, st>>>(A0, A1, bs0, bs1, Cg, Cd);
        }
    }

    cudaEventRecord(evJoin, s1);
    cudaStreamWaitEvent(0, evJoin, 0);
    // streams/events intentionally not destroyed: capture may still reference them
}

// round 12
// speedup vs baseline: 2.1971x; 1.0445x over previous
#include <cuda_runtime.h>
#include <cuda_fp16.h>
#include <math_constants.h>
#include <cstdint>

#define Ssz  50
#define NPT  3200
#define NROW 9600
#define ERT  160000
#define NB   1280

#define RSCALE   2048.0f          // residual scale 2^11
#define RINV     (1.0f/2048.0f)

// ================= static device scratch (no allocation) =================
static __device__ __half g_es0[(size_t)480000*256], g_es1[(size_t)480000*256];
static __device__ float g_gx0[(size_t)ERT*1024], g_gx1[(size_t)ERT*1024], g_gx2[(size_t)ERT*1024];
static __device__ float g_et0[(size_t)ERT*256],  g_et1[(size_t)ERT*256],  g_et2[(size_t)ERT*256];
static __device__ __half g_h0s[NROW*256], g_h1s[NROW*256];
static __device__ float g_c[NROW*256];
static __device__ float g_graw[(size_t)NROW*1024];
static __device__ float g_dec[(size_t)NROW*256];
static __device__ __half g_bs0[NB*256], g_bs1[NB*256];   // [Whh;W2] splits
static __device__ __half g_bp0[NB*256], g_bp1[NB*256];   // [Wih;W1] splits
static __device__ float g_bias[1024];

__device__ __forceinline__ float* gx_ptr(int t){ return (t==0)?g_gx0:((t==1)?g_gx1:g_gx2); }
__device__ __forceinline__ float* et_ptr(int t){ return (t==0)?g_et0:((t==1)?g_et1:g_et2); }
__device__ __forceinline__ void split2(float v, __half& a, __half& b){
    a = __float2half_rn(v);
    float r = v - __half2float(a);
    b = __float2half_rn(r * RSCALE);
}
__device__ __forceinline__ float fsig(float x){ return __fdividef(1.f, 1.f + __expf(-x)); }
__device__ __forceinline__ float ftanh(float x){ return 1.f - __fdividef(2.f, 1.f + __expf(2.f*x)); }

// ================= baseline-PTX tensor helpers =================
__device__ __forceinline__ uint32_t smem_u32(const void* p){
    uint32_t a;
    asm("{ .reg .u64 t; cvta.to.shared.u64 t, %1; cvt.u32.u64 %0, t; }" : "=r"(a) : "l"(p));
    return a;
}
__device__ __forceinline__ void ldsm4(uint32_t* r, uint32_t addr){
    asm volatile("ldmatrix.sync.aligned.m8n8.x4.shared.b16 {%0,%1,%2,%3}, [%4];"
        : "=r"(r[0]), "=r"(r[1]), "=r"(r[2]), "=r"(r[3]) : "r"(addr));
}
__device__ __forceinline__ void mma16816(float* c, const uint32_t* a, const uint32_t* b){
    asm volatile("mma.sync.aligned.m16n8k16.row.col.f32.f16.f16.f32 "
        "{%0,%1,%2,%3}, {%4,%5,%6,%7}, {%8,%9}, {%0,%1,%2,%3};"
        : "+f"(c[0]), "+f"(c[1]), "+f"(c[2]), "+f"(c[3])
        : "r"(a[0]), "r"(a[1]), "r"(a[2]), "r"(a[3]), "r"(b[0]), "r"(b[1]));
}
__device__ __forceinline__ void cpa16(uint32_t d, const void* s){
    asm volatile("cp.async.cg.shared.global [%0], [%1], 16;" :: "r"(d), "l"(s));
}
#define CP_COMMIT() asm volatile("cp.async.commit_group;" ::: "memory")
#define CP_WAIT0()  asm volatile("cp.async.wait_group 0;" ::: "memory")
#define CP_WAIT1()  asm volatile("cp.async.wait_group 1;" ::: "memory")

// ================= prep kernels =================
__global__ void pack_b_kernel(const float* __restrict__ Whh, const float* __restrict__ W2,
                              const float* __restrict__ Wih, const float* __restrict__ W1,
                              const float* __restrict__ bih, const float* __restrict__ bhh){
    int row = blockIdx.x, k = threadIdx.x, j = row*256 + k;
    float ws = (row < 1024) ? Whh[j] : W2[(size_t)(row-1024)*256 + k];
    float wp = (row < 1024) ? Wih[j] : W1[(size_t)(row-1024)*256 + k];
    split2(ws, g_bs0[j], g_bs1[j]);
    split2(wp, g_bp0[j], g_bp1[j]);
    if (row < 4) g_bias[j] = bih[j] + bhh[j];
}

// fused: split enc rows AND compute h0 = c0 = sum_s enc (enc read once)
__global__ void prep_kernel(const float* __restrict__ e0, const float* __restrict__ e1,
                            const float* __restrict__ e2){
    int r = blockIdx.x;                       // 0..9599
    int k = threadIdx.x;
    int t = r / NPT, n = r % NPT;
    const float* e = ((t==0)?e0:((t==1)?e1:e2)) + (size_t)n*(Ssz*256) + k;
    size_t wbase = ((size_t)t*ERT + (size_t)n*Ssz)*256 + k;
    float s = 0.f;
#pragma unroll 1
    for (int ss = 0; ss < Ssz; ss++){
        float v = e[ss*256];
        s += v;
        split2(v, g_es0[wbase + (size_t)ss*256], g_es1[wbase + (size_t)ss*256]);
    }
    g_c[r*256+k] = s;
    split2(s, g_h0s[r*256+k], g_h1s[r*256+k]);
}

// ================= emulated-fp32 GEMM via mma.sync fp16 (2-way split, 3 products) =================
// CTA tile 128x64, warp tile 32x32 (4x2 warps), 2 CTAs/SM.
// grid.x = n-block (fast -> co-resident CTAs share the A tile in L2), grid.y = m-block.
// Output split: n < 1024 -> Cg (width 1024), n >= 1024 -> Cd (width 256).
#define ASTR   72
#define ATILE  (128*ASTR*2)           // 18432 B
#define BTILE  (64*ASTR*2)            // 9216 B
#define STAGE  (2*ATILE + 2*BTILE)    // 55296 B : A0 A1 B0 B1
#define GSMEM  (2*STAGE)              // 110592 B

__global__ __launch_bounds__(256, 2) void gemm_kernel(
    const __half* __restrict__ A0, const __half* __restrict__ A1,
    const __half* __restrict__ B0, const __half* __restrict__ B1,
    float* __restrict__ Cg, float* __restrict__ Cd)
{
    extern __shared__ __half sh[];
    uint32_t sb = smem_u32(sh);

    const int tid = threadIdx.x, lane = tid & 31, w = tid >> 5;
    const int wm = w & 3, wn = w >> 2;
    const size_t m0 = (size_t)blockIdx.y * 128;
    const int n0 = blockIdx.x * 64;

    float acc0[2][4][4], acc1[2][4][4];
#pragma unroll
    for (int i = 0; i < 2; i++)
#pragma unroll
        for (int j = 0; j < 4; j++)
#pragma unroll
            for (int q = 0; q < 4; q++){ acc0[i][j][q] = 0.f; acc1[i][j][q] = 0.f; }

    const __half* Asrc[2] = { A0 + m0*256, A1 + m0*256 };
    const __half* Bsrc[2] = { B0 + (size_t)n0*256, B1 + (size_t)n0*256 };

    const int arow = wm*32 + (lane & 15);
    const int akof = (lane >> 4) * 8;
    const int brow = wn*32 + (lane & 7) + ((lane >> 4) << 3);
    const int bkof = ((lane >> 3) & 1) * 8;

    auto load_stage = [&](int c){
        uint32_t base = sb + (uint32_t)(c & 1)*STAGE;
#pragma unroll
        for (int t = 0; t < 2; t++){
            const __half* src = Asrc[t] + c*64;
#pragma unroll
            for (int i = 0; i < 4; i++){
                int id = tid + i*256, row = id >> 3, seg = id & 7;
                cpa16(base + t*ATILE + (uint32_t)(row*ASTR + seg*8)*2,
                      src + (size_t)row*256 + seg*8);
            }
        }
#pragma unroll
        for (int t = 0; t < 2; t++){
            const __half* src = Bsrc[t] + c*64;
#pragma unroll
            for (int i = 0; i < 2; i++){
                int id = tid + i*256, row = id >> 3, seg = id & 7;
                cpa16(base + 2*ATILE + t*BTILE + (uint32_t)(row*ASTR + seg*8)*2,
                      src + (size_t)row*256 + seg*8);
            }
        }
        CP_COMMIT();
    };

    load_stage(0);
#pragma unroll 1
    for (int c = 0; c < 4; c++){
        if (c + 1 < 4){ load_stage(c + 1); CP_WAIT1(); }
        else CP_WAIT0();
        __syncthreads();
        uint32_t base = sb + (uint32_t)(c & 1)*STAGE;
        uint32_t a0b = base, a1b = base + ATILE;
        uint32_t b0b = base + 2*ATILE, b1b = b0b + BTILE;
#pragma unroll
        for (int ks = 0; ks < 4; ks++){
            uint32_t b0f[4][2], b1f[4][2];
#pragma unroll
            for (int f2 = 0; f2 < 2; f2++){
                uint32_t off = (uint32_t)((brow + f2*16)*ASTR + ks*16 + bkof)*2;
                uint32_t r[4];
                ldsm4(r, b0b + off);
                b0f[f2*2][0] = r[0]; b0f[f2*2][1] = r[1];
                b0f[f2*2+1][0] = r[2]; b0f[f2*2+1][1] = r[3];
                ldsm4(r, b1b + off);
                b1f[f2*2][0] = r[0]; b1f[f2*2][1] = r[1];
                b1f[f2*2+1][0] = r[2]; b1f[f2*2+1][1] = r[3];
            }
#pragma unroll
            for (int fm = 0; fm < 2; fm++){
                uint32_t aoff = (uint32_t)((arow + fm*16)*ASTR + ks*16 + akof)*2;
                uint32_t a0f[4], a1f[4];
                ldsm4(a0f, a0b + aoff);
                ldsm4(a1f, a1b + aoff);
#pragma unroll
                for (int fn = 0; fn < 4; fn++){
                    mma16816(acc0[fm][fn], a0f, b0f[fn]);
                    mma16816(acc1[fm][fn], a0f, b1f[fn]);
                    mma16816(acc1[fm][fn], a1f, b0f[fn]);
                }
            }
        }
        __syncthreads();
    }

    // epilogue: route n<1024 -> Cg (w=1024), n>=1024 -> Cd (w=256)
    const bool isg = (n0 < 1024);
    float* Cb = isg ? Cg : Cd;
    const int cw = isg ? 1024 : 256;
    const int col = (isg ? n0 : (n0 - 1024)) + wn*32 + 2*(lane & 3);
#pragma unroll
    for (int fm = 0; fm < 2; fm++){
        size_t mrow = m0 + wm*32 + fm*16 + (lane >> 2);
        float* cp0 = Cb + mrow*cw     + col;
        float* cp1 = Cb + (mrow+8)*cw + col;
#pragma unroll
        for (int fn = 0; fn < 4; fn++){
            *(float2*)(cp0 + fn*8) = make_float2(fmaf(acc1[fm][fn][0], RINV, acc0[fm][fn][0]),
                                                 fmaf(acc1[fm][fn][1], RINV, acc0[fm][fn][1]));
            *(float2*)(cp1 + fn*8) = make_float2(fmaf(acc1[fm][fn][2], RINV, acc0[fm][fn][2]),
                                                 fmaf(acc1[fm][fn][3], RINV, acc0[fm][fn][3]));
        }
    }
}

// ================= cell0: initial cell (x=0, no gather) =================
__global__ __launch_bounds__(256) void cell0_kernel(){
    int k = threadIdx.x;
#pragma unroll
    for (int rr = 0; rr < 4; rr++){
        int r = blockIdx.x*4 + rr;
        const float* g = g_graw + (size_t)r*1024;
        float i = fsig (g[k]     + g_bias[k]);
        float f = fsig (g[256+k] + g_bias[256+k]);
        float gv= ftanh(g[512+k] + g_bias[512+k]);
        float o = fsig (g[768+k] + g_bias[768+k]);
        float cn = fmaf(f, g_c[r*256+k], i*gv);
        g_c[r*256+k] = cn;
        split2(o * ftanh(cn), g_h0s[r*256+k], g_h1s[r*256+k]);
    }
}

// per-s attention dot: u contribution of one s row (identical math/order to prior rounds)
__device__ __forceinline__ float attn_dot(float4 e0, float4 e1,
                                          const float* dec_s, const float* vt_s, int lane){
    float4 d0 = *(const float4*)(&dec_s[4*lane]);
    float4 d1 = *(const float4*)(&dec_s[128 + 4*lane]);
    float4 v0 = *(const float4*)(&vt_s[4*lane]);
    float4 v1 = *(const float4*)(&vt_s[128 + 4*lane]);
    float p0 = ftanh(e0.x + d0.x) * v0.x;
    float p1 = ftanh(e0.y + d0.y) * v0.y;
    p0 = fmaf(ftanh(e0.z + d0.z), v0.z, p0);
    p1 = fmaf(ftanh(e0.w + d0.w), v0.w, p1);
    p0 = fmaf(ftanh(e1.x + d1.x), v1.x, p0);
    p1 = fmaf(ftanh(e1.y + d1.y), v1.y, p1);
    p0 = fmaf(ftanh(e1.z + d1.z), v1.z, p0);
    p1 = fmaf(ftanh(e1.w + d1.w), v1.w, p1);
    return p0 + p1;
}

// ================= fused attention(step) + cell(step+1) =================
__global__ __launch_bounds__(256) void attn_cell_kernel(int step, int do_cell,
                                                        const float* __restrict__ vt,
                                                        float* __restrict__ out){
    __shared__ float dec_s[256], vt_s[256], u_s[Ssz];
    __shared__ int idx_sh;
    int tid = threadIdx.x, wid = tid >> 5, lane = tid & 31;
    int r = blockIdx.x;                       // global row 0..9599
    int t = r / NPT, n = r % NPT;
    dec_s[tid] = g_dec[(size_t)r*256 + tid];
    vt_s[tid]  = vt[tid];
    __syncthreads();

    const float* eb = et_ptr(t) + (size_t)n*Ssz*256;   // fully contiguous 51.2 KB
    // s values: wid + {0,8,16,24,32,40} (pairs, doubled MLP), then 48+wid for wid<2
#pragma unroll 1
    for (int s = wid; s + 8 < Ssz; s += 16){
        const float4* epA = (const float4*)(eb + (size_t)s*256);
        const float4* epB = (const float4*)(eb + (size_t)(s+8)*256);
        float4 a0 = epA[lane], a1 = epA[32 + lane];
        float4 b0 = epB[lane], b1 = epB[32 + lane];
        float pA = attn_dot(a0, a1, dec_s, vt_s, lane);
        float pB = attn_dot(b0, b1, dec_s, vt_s, lane);
#pragma unroll
        for (int off = 16; off; off >>= 1) pA += __shfl_xor_sync(0xffffffffu, pA, off);
#pragma unroll
        for (int off = 16; off; off >>= 1) pB += __shfl_xor_sync(0xffffffffu, pB, off);
        if (lane == 0){ u_s[s] = pA; u_s[s + 8] = pB; }
    }
    if (wid < 2){
        int s = 48 + wid;
        const float4* ep = (const float4*)(eb + (size_t)s*256);
        float4 e0 = ep[lane], e1 = ep[32 + lane];
        float p = attn_dot(e0, e1, dec_s, vt_s, lane);
#pragma unroll
        for (int off = 16; off; off >>= 1) p += __shfl_xor_sync(0xffffffffu, p, off);
        if (lane == 0) u_s[s] = p;
    }
    __syncthreads();

    if (wid == 0){
        float ua = u_s[lane];
        float ub = (lane + 32 < Ssz) ? u_s[lane + 32] : -CUDART_INF_F;
        float bm = ua; int bi = lane;
        if (ub > bm){ bm = ub; bi = lane + 32; }
#pragma unroll
        for (int off = 16; off; off >>= 1){
            float vm = __shfl_xor_sync(0xffffffffu, bm, off);
            int   vi = __shfl_xor_sync(0xffffffffu, bi, off);
            if (vm > bm || (vm == bm && vi < bi)){ bm = vm; bi = vi; }
        }
        float ea = __expf(ua - bm);
        float eb2 = (lane + 32 < Ssz) ? __expf(ub - bm) : 0.f;
        float sm = ea + eb2;
#pragma unroll
        for (int off = 16; off; off >>= 1) sm += __shfl_xor_sync(0xffffffffu, sm, off);
        float inv = 1.0f / sm;
        float* so = out + (size_t)t*8160000 + (size_t)n*2500 + step*50;
        so[lane] = ea * inv;
        if (lane + 32 < Ssz) so[lane + 32] = eb2 * inv;
        if (lane == 0){
            idx_sh = bi;
            out[(size_t)t*8160000 + 8000000 + (size_t)n*50 + step] = (float)bi;
        }
    }
    __syncthreads();

    if (do_cell){
        int k = tid;
        const float* g = g_graw + (size_t)r*1024;
        const float* ex = gx_ptr(t) + (size_t)(n*Ssz + idx_sh)*1024;
        float i = fsig (g[k]     + ex[k]     + g_bias[k]);
        float f = fsig (g[256+k] + ex[256+k] + g_bias[256+k]);
        float gv= ftanh(g[512+k] + ex[512+k] + g_bias[512+k]);
        float o = fsig (g[768+k] + ex[768+k] + g_bias[768+k]);
        float cn = fmaf(f, g_c[r*256+k], i*gv);
        g_c[r*256+k] = cn;
        split2(o * ftanh(cn), g_h0s[r*256+k], g_h1s[r*256+k]);
    }
}

// ================= launch =================
extern "C" void kernel_launch(void* const* d_in, const int* in_sizes, int n_in,
                              void* d_out, int out_size){
    const float* home = (const float*)d_in[0];
    const float* vis  = (const float*)d_in[1];
    const float* team = (const float*)d_in[2];
    const float* Wih  = (const float*)d_in[3];
    const float* Whh  = (const float*)d_in[4];
    const float* bih  = (const float*)d_in[5];
    const float* bhh  = (const float*)d_in[6];
    const float* W1   = (const float*)d_in[7];
    const float* W2   = (const float*)d_in[8];
    const float* vt   = (const float*)d_in[9];
    float* out = (float*)d_out;

    cudaFuncSetAttribute(gemm_kernel, cudaFuncAttributeMaxDynamicSharedMemorySize, GSMEM);

    pack_b_kernel<<<NB, 256>>>(Whh, W2, Wih, W1, bih, bhh);
    prep_kernel<<<NROW, 256>>>(home, vis, team);

    __half *es0, *es1, *bp0, *bp1, *bs0, *bs1, *h0, *h1;
    float *gx0, *gx1, *gx2, *et0, *et1, *et2, *graw, *dec;
    cudaGetSymbolAddress((void**)&es0, g_es0);  cudaGetSymbolAddress((void**)&es1, g_es1);
    cudaGetSymbolAddress((void**)&bp0, g_bp0);  cudaGetSymbolAddress((void**)&bp1, g_bp1);
    cudaGetSymbolAddress((void**)&bs0, g_bs0);  cudaGetSymbolAddress((void**)&bs1, g_bs1);
    cudaGetSymbolAddress((void**)&h0,  g_h0s);  cudaGetSymbolAddress((void**)&h1,  g_h1s);
    cudaGetSymbolAddress((void**)&gx0, g_gx0);  cudaGetSymbolAddress((void**)&gx1, g_gx1);
    cudaGetSymbolAddress((void**)&gx2, g_gx2);
    cudaGetSymbolAddress((void**)&et0, g_et0);  cudaGetSymbolAddress((void**)&et1, g_et1);
    cudaGetSymbolAddress((void**)&et2, g_et2);
    cudaGetSymbolAddress((void**)&graw, g_graw); cudaGetSymbolAddress((void**)&dec, g_dec);

    float* gxs[3] = {gx0, gx1, gx2};
    float* ets[3] = {et0, et1, et2};
    for (int t = 0; t < 3; t++){
        size_t off = (size_t)t * ERT * 256;
        gemm_kernel<<<dim3(20, 1250), 256, GSMEM>>>(es0 + off, es1 + off, bp0, bp1,
                                                    gxs[t], ets[t]);
    }

    // bootstrap: gates from h0 -> cell0 -> gates+dec
    gemm_kernel<<<dim3(20, 75), 256, GSMEM>>>(h0, h1, bs0, bs1, graw, dec);
    cell0_kernel<<<NROW/4, 256>>>();
    gemm_kernel<<<dim3(20, 75), 256, GSMEM>>>(h0, h1, bs0, bs1, graw, dec);

    for (int i = 0; i < Ssz; i++){
        attn_cell_kernel<<<NROW, 256>>>(i, (i + 1 < Ssz) ? 1 : 0, vt, out);
        if (i + 1 < Ssz)
            gemm_kernel<<<dim3(20, 75), 256, GSMEM>>>(h0, h1, bs0, bs1, graw, dec);
    }
}